// round 2
// baseline (speedup 1.0000x reference)
#include <cuda_runtime.h>

// Problem: B=16, Te=1024, Td=1024, D=1024
//   S[b,e,t]   = sum_d enc[b,e,d] * dec[b,t,d]          (GEMM NT)
//   A[b,e,t]   = softmax_e S[b,e,t]                     (softmax over axis e)
//   ctx[b,t,d] = sum_e A[b,e,t] * enc[b,e,d]            (GEMM TN)
//   out[b,t,:] = concat(dec[b,t,:], ctx[b,t,:])         ([B, Td, 2048])

namespace cfg {
constexpr int NB = 16;
constexpr int TE = 1024;
constexpr int TD = 1024;
constexpr int DD = 1024;
constexpr int BM = 128, BN = 128, BK = 16;
constexpr int SST = 132;  // padded smem row stride (floats), keeps 16B alignment
}

// 64MB scratch for scores / attention weights (device global: allocation-free)
__device__ float g_S[(size_t)cfg::NB * cfg::TE * cfg::TD];

// ---------------------------------------------------------------------------
// GEMM 1 (NT): S[e,t] = sum_d enc[e,d] * dec[t,d]   (both operands K-major)
// ---------------------------------------------------------------------------
__global__ __launch_bounds__(256) void gemm_nt_kernel(
    const float* __restrict__ enc, const float* __restrict__ dec) {
  using namespace cfg;
  __shared__ float As[BK][SST];
  __shared__ float Bs[BK][SST];

  const int b = blockIdx.z;
  const float* Ab = enc + (size_t)b * TE * DD;
  const float* Bb = dec + (size_t)b * TD * DD;
  float* Cb = g_S + (size_t)b * TE * TD;

  const int tid = threadIdx.x;
  const int tx = tid & 15;        // 0..15 -> 8 cols each
  const int ty = tid >> 4;        // 0..15 -> 8 rows each
  const int row0 = blockIdx.y * BM;
  const int col0 = blockIdx.x * BN;

  // loader mapping: 512 float4 per tile, 2 per thread
  const int lrow = tid >> 2;          // 0..63
  const int lk   = (tid & 3) * 4;     // 0,4,8,12

  float acc[8][8];
#pragma unroll
  for (int i = 0; i < 8; ++i)
#pragma unroll
    for (int j = 0; j < 8; ++j) acc[i][j] = 0.f;

  for (int k0 = 0; k0 < DD; k0 += BK) {
#pragma unroll
    for (int h = 0; h < 2; ++h) {
      const int r = lrow + h * 64;
      float4 fa = *reinterpret_cast<const float4*>(
          &Ab[(size_t)(row0 + r) * DD + k0 + lk]);
      As[lk + 0][r] = fa.x; As[lk + 1][r] = fa.y;
      As[lk + 2][r] = fa.z; As[lk + 3][r] = fa.w;
      float4 fb = *reinterpret_cast<const float4*>(
          &Bb[(size_t)(col0 + r) * DD + k0 + lk]);
      Bs[lk + 0][r] = fb.x; Bs[lk + 1][r] = fb.y;
      Bs[lk + 2][r] = fb.z; Bs[lk + 3][r] = fb.w;
    }
    __syncthreads();
#pragma unroll
    for (int k = 0; k < BK; ++k) {
      float4 a0 = *reinterpret_cast<const float4*>(&As[k][ty * 8]);
      float4 a1 = *reinterpret_cast<const float4*>(&As[k][ty * 8 + 4]);
      float4 b0 = *reinterpret_cast<const float4*>(&Bs[k][tx * 8]);
      float4 b1 = *reinterpret_cast<const float4*>(&Bs[k][tx * 8 + 4]);
      float ra[8] = {a0.x, a0.y, a0.z, a0.w, a1.x, a1.y, a1.z, a1.w};
      float rb[8] = {b0.x, b0.y, b0.z, b0.w, b1.x, b1.y, b1.z, b1.w};
#pragma unroll
      for (int i = 0; i < 8; ++i)
#pragma unroll
        for (int j = 0; j < 8; ++j) acc[i][j] += ra[i] * rb[j];
    }
    __syncthreads();
  }

#pragma unroll
  for (int i = 0; i < 8; ++i) {
    float4* cp = reinterpret_cast<float4*>(
        &Cb[(size_t)(row0 + ty * 8 + i) * TD + col0 + tx * 8]);
    cp[0] = make_float4(acc[i][0], acc[i][1], acc[i][2], acc[i][3]);
    cp[1] = make_float4(acc[i][4], acc[i][5], acc[i][6], acc[i][7]);
  }
}

// ---------------------------------------------------------------------------
// Softmax over e (axis=1) for each (b, t). Block: 32 t-columns x 8 e-lanes.
// ---------------------------------------------------------------------------
__global__ __launch_bounds__(256) void softmax_e_kernel() {
  using namespace cfg;
  const int b = blockIdx.y;
  const int t0 = blockIdx.x * 32;
  const int tx = threadIdx.x;  // column within group (coalesced)
  const int ty = threadIdx.y;  // e-stride lane
  float* Sb = g_S + (size_t)b * TE * TD;

  float m = -3.402823466e+38f;
  float s = 0.f;
  for (int e = ty; e < TE; e += 8) {
    float v = Sb[(size_t)e * TD + t0 + tx];
    float mn = fmaxf(m, v);
    s = s * __expf(m - mn) + __expf(v - mn);
    m = mn;
  }
  __shared__ float sm[8][32];
  __shared__ float ss[8][32];
  sm[ty][tx] = m;
  ss[ty][tx] = s;
  __syncthreads();
  if (ty == 0) {
    float M = sm[0][tx], S = ss[0][tx];
#pragma unroll
    for (int i = 1; i < 8; ++i) {
      float mi = sm[i][tx], si = ss[i][tx];
      float mn = fmaxf(M, mi);
      S = S * __expf(M - mn) + si * __expf(mi - mn);
      M = mn;
    }
    sm[0][tx] = M;
    ss[0][tx] = 1.f / S;
  }
  __syncthreads();
  const float M = sm[0][tx];
  const float inv = ss[0][tx];
  for (int e = ty; e < TE; e += 8) {
    const size_t idx = (size_t)e * TD + t0 + tx;
    Sb[idx] = __expf(Sb[idx] - M) * inv;
  }
}

// ---------------------------------------------------------------------------
// GEMM 2 (TN): ctx[t,d] = sum_e attn[e,t] * enc[e,d]; writes out[...,1024+d]
// ---------------------------------------------------------------------------
__global__ __launch_bounds__(256) void gemm_tn_kernel(
    const float* __restrict__ enc, float* __restrict__ out) {
  using namespace cfg;
  __shared__ float As[BK][SST];
  __shared__ float Bs[BK][SST];

  const int b = blockIdx.z;
  const float* Ab = g_S + (size_t)b * TE * TD;   // attn [e, t]
  const float* Bb = enc + (size_t)b * TE * DD;   // enc  [e, d]
  float* Ob = out + (size_t)b * TD * 2048;

  const int tid = threadIdx.x;
  const int tx = tid & 15;
  const int ty = tid >> 4;
  const int m0 = blockIdx.y * BM;  // t
  const int n0 = blockIdx.x * BN;  // d

  const int lkr = tid >> 5;           // 0..7 (k row)
  const int lc4 = (tid & 31) * 4;     // 0..124 (col, float4)

  float acc[8][8];
#pragma unroll
  for (int i = 0; i < 8; ++i)
#pragma unroll
    for (int j = 0; j < 8; ++j) acc[i][j] = 0.f;

  for (int k0 = 0; k0 < TE; k0 += BK) {
#pragma unroll
    for (int h = 0; h < 2; ++h) {
      const int k = lkr + h * 8;
      float4 fa = *reinterpret_cast<const float4*>(
          &Ab[(size_t)(k0 + k) * TD + m0 + lc4]);
      *reinterpret_cast<float4*>(&As[k][lc4]) = fa;
      float4 fb = *reinterpret_cast<const float4*>(
          &Bb[(size_t)(k0 + k) * DD + n0 + lc4]);
      *reinterpret_cast<float4*>(&Bs[k][lc4]) = fb;
    }
    __syncthreads();
#pragma unroll
    for (int k = 0; k < BK; ++k) {
      float4 a0 = *reinterpret_cast<const float4*>(&As[k][ty * 8]);
      float4 a1 = *reinterpret_cast<const float4*>(&As[k][ty * 8 + 4]);
      float4 b0 = *reinterpret_cast<const float4*>(&Bs[k][tx * 8]);
      float4 b1 = *reinterpret_cast<const float4*>(&Bs[k][tx * 8 + 4]);
      float ra[8] = {a0.x, a0.y, a0.z, a0.w, a1.x, a1.y, a1.z, a1.w};
      float rb[8] = {b0.x, b0.y, b0.z, b0.w, b1.x, b1.y, b1.z, b1.w};
#pragma unroll
      for (int i = 0; i < 8; ++i)
#pragma unroll
        for (int j = 0; j < 8; ++j) acc[i][j] += ra[i] * rb[j];
    }
    __syncthreads();
  }

#pragma unroll
  for (int i = 0; i < 8; ++i) {
    float4* cp = reinterpret_cast<float4*>(
        &Ob[(size_t)(m0 + ty * 8 + i) * 2048 + 1024 + n0 + tx * 8]);
    cp[0] = make_float4(acc[i][0], acc[i][1], acc[i][2], acc[i][3]);
    cp[1] = make_float4(acc[i][4], acc[i][5], acc[i][6], acc[i][7]);
  }
}

// ---------------------------------------------------------------------------
// Copy decoder_outputs into out[..., 0:1024]
// ---------------------------------------------------------------------------
__global__ __launch_bounds__(256) void copy_dec_kernel(
    const float4* __restrict__ dec, float4* __restrict__ out) {
  using namespace cfg;
  const size_t i = (size_t)blockIdx.x * blockDim.x + threadIdx.x;
  // dec: B*Td rows x 256 float4; out rows are 512 float4, first 256 = dec
  const size_t row = i >> 8;
  const size_t c = i & 255;
  out[row * 512 + c] = dec[i];
}

// ---------------------------------------------------------------------------
extern "C" void kernel_launch(void* const* d_in, const int* in_sizes, int n_in,
                              void* d_out, int out_size) {
  using namespace cfg;
  const float* enc = (const float*)d_in[0];
  const float* dec = (const float*)d_in[1];
  float* out = (float*)d_out;

  dim3 blk(256);
  dim3 g1(TD / BN, TE / BM, NB);
  gemm_nt_kernel<<<g1, blk>>>(enc, dec);

  dim3 gs(TD / 32, NB);
  dim3 bsm(32, 8);
  softmax_e_kernel<<<gs, bsm>>>();

  dim3 g2(DD / BN, TD / BM, NB);
  gemm_tn_kernel<<<g2, blk>>>(enc, out);

  const size_t n4 = (size_t)NB * TD * DD / 4;  // float4 count
  copy_dec_kernel<<<(unsigned)(n4 / 256), 256>>>(
      (const float4*)dec, (float4*)out);
}

// round 4
// speedup vs baseline: 2.4273x; 2.4273x over previous
#include <cuda_runtime.h>
#include <cuda_bf16.h>
#include <cstdint>

// B=16, Te=1024, Td=1024, D=1024
//   S[b,e,t]   = enc[b,e,:] . dec[b,t,:]          (GEMM1, M=e, N=t, K=d)
//   A          = softmax_e(S)
//   ctx[b,t,d] = sum_e A[e,t] enc[e,d]            (GEMM2, M=t, N=e(K), via attn^T, enc^T panels)
//   out        = concat(dec, ctx)                 [B, Td, 2048]
//
// GEMMs on tensor cores via mma.sync bf16 (baseline PTX, works at compute_103):
//   a*b ~= ah*bh + ah*bl + al*bh  (hi/lo bf16 split, fp32 accumulate)

#define PANEL_U4 1024  // one 128x64-bf16 SW128 panel = 16KB = 1024 uint4
#define NPANEL 2048    // 16 b * 8 rowblk * 16 kblk

__device__ float g_S[(size_t)16 * 1024 * 1024];  // fp32 scores
__device__ uint4 g_encPh[NPANEL * PANEL_U4], g_encPl[NPANEL * PANEL_U4];  // enc [e,d]
__device__ uint4 g_decPh[NPANEL * PANEL_U4], g_decPl[NPANEL * PANEL_U4];  // dec [t,d]
__device__ uint4 g_encTh[NPANEL * PANEL_U4], g_encTl[NPANEL * PANEL_U4];  // enc^T [d,e]
__device__ uint4 g_attTh[NPANEL * PANEL_U4], g_attTl[NPANEL * PANEL_U4];  // attn^T [t,e]

// ---------------------------------------------------------------------------
static __device__ __forceinline__ uint32_t smem_u32(const void* p) {
  uint32_t a;
  asm("{ .reg .u64 t; cvta.to.shared.u64 t, %1; cvt.u32.u64 %0, t; }"
      : "=r"(a) : "l"(p));
  return a;
}
static __device__ __forceinline__ uint32_t swz(uint32_t x) {
  return x ^ ((x >> 3) & 0x70);
}
static __device__ __forceinline__ void cp_async16(uint32_t dst,
                                                  const void* src) {
  asm volatile("cp.async.cg.shared.global [%0], [%1], 16;"
               :: "r"(dst), "l"(src) : "memory");
}
static __device__ __forceinline__ void ldsm4(uint32_t* r, uint32_t addr) {
  asm volatile(
      "ldmatrix.sync.aligned.m8n8.x4.shared.b16 {%0,%1,%2,%3}, [%4];"
      : "=r"(r[0]), "=r"(r[1]), "=r"(r[2]), "=r"(r[3])
      : "r"(addr));
}
static __device__ __forceinline__ void mma16816(float* c, const uint32_t* a,
                                                const uint32_t* b) {
  asm volatile(
      "mma.sync.aligned.m16n8k16.row.col.f32.bf16.bf16.f32 "
      "{%0,%1,%2,%3}, {%4,%5,%6,%7}, {%8,%9}, {%0,%1,%2,%3};"
      : "+f"(c[0]), "+f"(c[1]), "+f"(c[2]), "+f"(c[3])
      : "r"(a[0]), "r"(a[1]), "r"(a[2]), "r"(a[3]), "r"(b[0]), "r"(b[1]));
}
static __device__ __forceinline__ void split8(const float* f, uint4& H,
                                              uint4& L) {
  uint32_t h[4], l[4];
#pragma unroll
  for (int j = 0; j < 4; ++j) {
    __nv_bfloat16 h0 = __float2bfloat16(f[2 * j]);
    __nv_bfloat16 h1 = __float2bfloat16(f[2 * j + 1]);
    __nv_bfloat16 l0 = __float2bfloat16(f[2 * j] - __bfloat162float(h0));
    __nv_bfloat16 l1 = __float2bfloat16(f[2 * j + 1] - __bfloat162float(h1));
    h[j] = (uint32_t)__bfloat16_as_ushort(h0) |
           ((uint32_t)__bfloat16_as_ushort(h1) << 16);
    l[j] = (uint32_t)__bfloat16_as_ushort(l0) |
           ((uint32_t)__bfloat16_as_ushort(l1) << 16);
  }
  H = make_uint4(h[0], h[1], h[2], h[3]);
  L = make_uint4(l[0], l[1], l[2], l[3]);
}

// ---------------------------------------------------------------------------
// Pack: fp32 [rows,1024] -> SW128 bf16 hi/lo panels. grid (kb16, rb8, b16).
// which: 0 = enc->encP, 1 = dec->decP
// ---------------------------------------------------------------------------
__global__ __launch_bounds__(256) void conv_split_kernel(
    const float* __restrict__ src, int which) {
  uint4* dh = which ? g_decPh : g_encPh;
  uint4* dl = which ? g_decPl : g_encPl;
  const int kb = blockIdx.x, rb = blockIdx.y, b = blockIdx.z;
  const size_t panel = ((size_t)(b * 8 + rb) * 16 + kb) * PANEL_U4;
  const float* sp = src + ((size_t)b * 1024 + rb * 128) * 1024 + kb * 64;
#pragma unroll
  for (int it = 0; it < 4; ++it) {
    const int chunk = it * 256 + threadIdx.x;
    const int r = chunk >> 3, cc = chunk & 7;
    const float4* s4 =
        reinterpret_cast<const float4*>(sp + (size_t)r * 1024 + cc * 8);
    float4 x0 = s4[0], x1 = s4[1];
    float f[8] = {x0.x, x0.y, x0.z, x0.w, x1.x, x1.y, x1.z, x1.w};
    uint4 H, L;
    split8(f, H, L);
    const uint32_t off = swz((uint32_t)(r * 128 + cc * 16)) >> 4;
    dh[panel + off] = H;
    dl[panel + off] = L;
  }
}

// transpose pack: enc [e,d] -> encT panels over [d-rowblk][e-kblk]
__global__ __launch_bounds__(256) void conv_split_T_kernel(
    const float* __restrict__ src) {
  const int eb = blockIdx.x, db = blockIdx.y, b = blockIdx.z;
  __shared__ float tile[64 * 132];
  const float* sp = src + ((size_t)b * 1024 + eb * 64) * 1024 + db * 128;
#pragma unroll
  for (int it = 0; it < 8; ++it) {
    const int idx = it * 256 + threadIdx.x;
    const int e = idx >> 5, c4 = idx & 31;
    float4 v = *reinterpret_cast<const float4*>(sp + (size_t)e * 1024 + c4 * 4);
    *reinterpret_cast<float4*>(tile + e * 132 + c4 * 4) = v;
  }
  __syncthreads();
  const size_t panel = ((size_t)(b * 8 + db) * 16 + eb) * PANEL_U4;
#pragma unroll
  for (int it = 0; it < 4; ++it) {
    const int chunk = it * 256 + threadIdx.x;
    const int d = chunk >> 3, ec = chunk & 7;
    float f[8];
#pragma unroll
    for (int j = 0; j < 8; ++j) f[j] = tile[(ec * 8 + j) * 132 + d];
    uint4 H, L;
    split8(f, H, L);
    const uint32_t off = swz((uint32_t)(d * 128 + ec * 16)) >> 4;
    g_encTh[panel + off] = H;
    g_encTl[panel + off] = L;
  }
}

// ---------------------------------------------------------------------------
// Softmax over e + transpose + bf16 hi/lo pack of attn^T [t,e]
// grid (tchunk=16, b=16), block (64,4)
// ---------------------------------------------------------------------------
__global__ __launch_bounds__(256) void softmax_pack_kernel() {
  const int b = blockIdx.y;
  const int t0 = blockIdx.x * 64;
  const int tx = threadIdx.x, ty = threadIdx.y;
  const int ltid = ty * 64 + tx;
  const float* Sb = g_S + (size_t)b * 1024 * 1024;
  __shared__ float sm[4][64], ss[4][64], Mv[64], Iv[64];
  __shared__ float tile[64 * 68];

  float m = -3.402823466e38f, s = 0.f;
  for (int e = ty; e < 1024; e += 4) {
    float v = Sb[(size_t)e * 1024 + t0 + tx];
    float mn = fmaxf(m, v);
    s = s * __expf(m - mn) + __expf(v - mn);
    m = mn;
  }
  sm[ty][tx] = m;
  ss[ty][tx] = s;
  __syncthreads();
  if (ty == 0) {
    float M = sm[0][tx], S = ss[0][tx];
#pragma unroll
    for (int i = 1; i < 4; ++i) {
      float mi = sm[i][tx], si = ss[i][tx];
      float mn = fmaxf(M, mi);
      S = S * __expf(M - mn) + si * __expf(mi - mn);
      M = mn;
    }
    Mv[tx] = M;
    Iv[tx] = 1.f / S;
  }
  __syncthreads();

  const int tb = t0 >> 7;
  const int tl0 = t0 & 127;
  for (int eb = 0; eb < 16; ++eb) {
#pragma unroll
    for (int it = 0; it < 4; ++it) {
      const int idx = it * 256 + ltid;
      const int e = idx >> 4, c4 = idx & 15;
      float4 v = *reinterpret_cast<const float4*>(
          Sb + (size_t)(eb * 64 + e) * 1024 + t0 + c4 * 4);
      const int t = c4 * 4;
      float4 p;
      p.x = __expf(v.x - Mv[t + 0]) * Iv[t + 0];
      p.y = __expf(v.y - Mv[t + 1]) * Iv[t + 1];
      p.z = __expf(v.z - Mv[t + 2]) * Iv[t + 2];
      p.w = __expf(v.w - Mv[t + 3]) * Iv[t + 3];
      *reinterpret_cast<float4*>(tile + e * 68 + c4 * 4) = p;
    }
    __syncthreads();
    const size_t panel = ((size_t)(b * 8 + tb) * 16 + eb) * PANEL_U4;
#pragma unroll
    for (int it = 0; it < 2; ++it) {
      const int chunk = it * 256 + ltid;
      const int tl = chunk >> 3, ec = chunk & 7;
      float f[8];
#pragma unroll
      for (int j = 0; j < 8; ++j) f[j] = tile[(ec * 8 + j) * 68 + tl];
      uint4 H, L;
      split8(f, H, L);
      const uint32_t off = swz((uint32_t)((tl0 + tl) * 128 + ec * 16)) >> 4;
      g_attTh[panel + off] = H;
      g_attTl[panel + off] = L;
    }
    __syncthreads();
  }
}

// ---------------------------------------------------------------------------
// HMMA GEMM: C[128,128] fp32 += A[128,1024] * B[128,1024]^T via bf16 split.
// grid (nb=8, mb=8, b=16), 256 threads (8 warps: 4 m-groups x 2 n-groups),
// BK=64, double-buffered cp.async (2 x 64KB smem).
// which: 0 = GEMM1 (encP x decP -> g_S), 1 = GEMM2 (attT x encT -> out ctx)
// ---------------------------------------------------------------------------
__global__ __launch_bounds__(256) void hmma_gemm_kernel(float* __restrict__ o,
                                                        int which) {
  extern __shared__ __align__(16) char dsm[];
  const uint4 *Ah, *Al, *Bh, *Bl;
  float* C;
  int ldc, coff;
  size_t bstride;
  if (which == 0) {
    Ah = g_encPh; Al = g_encPl; Bh = g_decPh; Bl = g_decPl;
    C = g_S; ldc = 1024; coff = 0; bstride = (size_t)1024 * 1024;
  } else {
    Ah = g_attTh; Al = g_attTl; Bh = g_encTh; Bl = g_encTl;
    C = o; ldc = 2048; coff = 1024; bstride = (size_t)1024 * 2048;
  }

  const int tid = threadIdx.x;
  const int wid = tid >> 5, lane = tid & 31;
  const int wm = wid & 3, wn = wid >> 2;  // warp tile: rows wm*32, cols wn*64
  const int b = blockIdx.z, mbk = blockIdx.y, nbk = blockIdx.x;
  const size_t apan = ((size_t)(b * 8 + mbk)) * 16;
  const size_t bpan = ((size_t)(b * 8 + nbk)) * 16;
  const uint32_t smem_base = smem_u32(dsm);

  auto issue_chunk = [&](int c) {
    const uint32_t dbase = smem_base + (uint32_t)(c & 1) * 65536u;
    const uint4* g0 = Ah + (apan + c) * PANEL_U4;
    const uint4* g1 = Al + (apan + c) * PANEL_U4;
    const uint4* g2 = Bh + (bpan + c) * PANEL_U4;
    const uint4* g3 = Bl + (bpan + c) * PANEL_U4;
#pragma unroll
    for (int j = 0; j < 4; ++j) {
      const int i = tid + j * 256;
      cp_async16(dbase + 0u * 16384u + (uint32_t)i * 16u, g0 + i);
      cp_async16(dbase + 1u * 16384u + (uint32_t)i * 16u, g1 + i);
      cp_async16(dbase + 2u * 16384u + (uint32_t)i * 16u, g2 + i);
      cp_async16(dbase + 3u * 16384u + (uint32_t)i * 16u, g3 + i);
    }
    asm volatile("cp.async.commit_group;" ::: "memory");
  };

  float acc[2][8][4];
#pragma unroll
  for (int mt = 0; mt < 2; ++mt)
#pragma unroll
    for (int nt = 0; nt < 8; ++nt)
#pragma unroll
      for (int j = 0; j < 4; ++j) acc[mt][nt][j] = 0.f;

  issue_chunk(0);
  issue_chunk(1);

  // per-lane ldmatrix address components (byte offsets inside a panel)
  const uint32_t a_row = (uint32_t)(wm * 32 + (lane & 15));
  const uint32_t a_koff = (lane & 16) ? 16u : 0u;
  const uint32_t b_row = (uint32_t)(wn * 64 + (lane & 7) + ((lane & 16) ? 8 : 0));
  const uint32_t b_koff = (lane & 8) ? 16u : 0u;

  for (int c = 0; c < 16; ++c) {
    asm volatile("cp.async.wait_group 1;" ::: "memory");
    __syncthreads();
    const uint32_t sb = smem_base + (uint32_t)(c & 1) * 65536u;
    const uint32_t Ah_b = sb, Al_b = sb + 16384u;
    const uint32_t Bh_b = sb + 32768u, Bl_b = sb + 49152u;

#pragma unroll
    for (int kk = 0; kk < 4; ++kk) {
      uint32_t ah[2][4], al[2][4];
#pragma unroll
      for (int mt = 0; mt < 2; ++mt) {
        const uint32_t byte =
            swz((a_row + (uint32_t)mt * 16u) * 128u + (uint32_t)kk * 32u + a_koff);
        ldsm4(ah[mt], Ah_b + byte);
        ldsm4(al[mt], Al_b + byte);
      }
      uint32_t bh[4][4], bl[4][4];
#pragma unroll
      for (int np = 0; np < 4; ++np) {
        const uint32_t byte =
            swz((b_row + (uint32_t)np * 16u) * 128u + (uint32_t)kk * 32u + b_koff);
        ldsm4(bh[np], Bh_b + byte);
        ldsm4(bl[np], Bl_b + byte);
      }
#pragma unroll
      for (int mt = 0; mt < 2; ++mt)
#pragma unroll
        for (int nt = 0; nt < 8; ++nt) {
          const uint32_t* B0 = &bh[nt >> 1][(nt & 1) * 2];
          const uint32_t* B1 = &bl[nt >> 1][(nt & 1) * 2];
          mma16816(acc[mt][nt], ah[mt], B0);
          mma16816(acc[mt][nt], ah[mt], B1);
          mma16816(acc[mt][nt], al[mt], B0);
        }
    }
    __syncthreads();
    if (c + 2 < 16) issue_chunk(c + 2);
  }

  // epilogue: direct fp32 stores (32B sectors, fully utilized)
  float* Cb = C + (size_t)b * bstride + (size_t)(mbk * 128) * ldc + coff +
              nbk * 128;
  const int g = lane >> 2, tig = lane & 3;
#pragma unroll
  for (int mt = 0; mt < 2; ++mt)
#pragma unroll
    for (int nt = 0; nt < 8; ++nt) {
      const int row = wm * 32 + mt * 16 + g;
      const int col = wn * 64 + nt * 8 + tig * 2;
      *reinterpret_cast<float2*>(Cb + (size_t)row * ldc + col) =
          make_float2(acc[mt][nt][0], acc[mt][nt][1]);
      *reinterpret_cast<float2*>(Cb + (size_t)(row + 8) * ldc + col) =
          make_float2(acc[mt][nt][2], acc[mt][nt][3]);
    }
}

// ---------------------------------------------------------------------------
__global__ __launch_bounds__(256) void copy_dec_kernel(
    const float4* __restrict__ dec, float4* __restrict__ out) {
  const size_t i = (size_t)blockIdx.x * blockDim.x + threadIdx.x;
  const size_t row = i >> 8;
  const size_t c = i & 255;
  out[row * 512 + c] = dec[i];
}

// ---------------------------------------------------------------------------
extern "C" void kernel_launch(void* const* d_in, const int* in_sizes, int n_in,
                              void* d_out, int out_size) {
  const float* enc = (const float*)d_in[0];
  const float* dec = (const float*)d_in[1];
  float* out = (float*)d_out;

  static bool configured = false;
  if (!configured) {
    cudaFuncSetAttribute(hmma_gemm_kernel,
                         cudaFuncAttributeMaxDynamicSharedMemorySize, 131072);
    configured = true;
  }

  dim3 cg(16, 8, 16);
  conv_split_kernel<<<cg, 256>>>(enc, 0);
  conv_split_kernel<<<cg, 256>>>(dec, 1);
  conv_split_T_kernel<<<cg, 256>>>(enc);

  dim3 gg(8, 8, 16);
  hmma_gemm_kernel<<<gg, 256, 131072>>>(out, 0);

  dim3 gs(16, 16);
  softmax_pack_kernel<<<gs, dim3(64, 4)>>>();

  hmma_gemm_kernel<<<gg, 256, 131072>>>(out, 1);

  const size_t n4 = (size_t)16 * 1024 * 1024 / 4;
  copy_dec_kernel<<<(unsigned)(n4 / 256), 256>>>((const float4*)dec,
                                                 (float4*)out);
}

// round 5
// speedup vs baseline: 2.5037x; 1.0315x over previous
#include <cuda_runtime.h>
#include <cuda_bf16.h>
#include <cstdint>

// B=16, Te=1024, Td=1024, D=1024
//   S[b,e,t]   = enc[b,e,:] . dec[b,t,:]          (GEMM1)
//   A          = softmax_e(S)
//   ctx[b,t,d] = sum_e A[e,t] enc[e,d]            (GEMM2 via attn^T, enc^T panels)
//   out        = concat(dec, ctx)                 [B, Td, 2048]
//
// GEMMs on tensor cores via mma.sync bf16 (hi/lo split, fp32 accumulate):
//   a*b ~= ah*bh + ah*bl + al*bh

#define PANEL_U4 1024  // one 128x64-bf16 SW128 panel = 16KB = 1024 uint4
#define NPANEL 2048    // 16 b * 8 rowblk * 16 kblk

__device__ float g_S[(size_t)16 * 1024 * 1024];  // fp32 scores
__device__ uint4 g_encPh[NPANEL * PANEL_U4], g_encPl[NPANEL * PANEL_U4];  // enc [e,d]
__device__ uint4 g_decPh[NPANEL * PANEL_U4], g_decPl[NPANEL * PANEL_U4];  // dec [t,d]
__device__ uint4 g_encTh[NPANEL * PANEL_U4], g_encTl[NPANEL * PANEL_U4];  // enc^T [d,e]
__device__ uint4 g_attTh[NPANEL * PANEL_U4], g_attTl[NPANEL * PANEL_U4];  // attn^T [t,e]

// ---------------------------------------------------------------------------
static __device__ __forceinline__ uint32_t smem_u32(const void* p) {
  uint32_t a;
  asm("{ .reg .u64 t; cvta.to.shared.u64 t, %1; cvt.u32.u64 %0, t; }"
      : "=r"(a) : "l"(p));
  return a;
}
static __device__ __forceinline__ uint32_t swz(uint32_t x) {
  return x ^ ((x >> 3) & 0x70);
}
static __device__ __forceinline__ void cp_async16(uint32_t dst,
                                                  const void* src) {
  asm volatile("cp.async.cg.shared.global [%0], [%1], 16;"
               :: "r"(dst), "l"(src) : "memory");
}
static __device__ __forceinline__ void ldsm4(uint32_t* r, uint32_t addr) {
  asm volatile(
      "ldmatrix.sync.aligned.m8n8.x4.shared.b16 {%0,%1,%2,%3}, [%4];"
      : "=r"(r[0]), "=r"(r[1]), "=r"(r[2]), "=r"(r[3])
      : "r"(addr));
}
static __device__ __forceinline__ void mma16816(float* c, const uint32_t* a,
                                                const uint32_t* b) {
  asm volatile(
      "mma.sync.aligned.m16n8k16.row.col.f32.bf16.bf16.f32 "
      "{%0,%1,%2,%3}, {%4,%5,%6,%7}, {%8,%9}, {%0,%1,%2,%3};"
      : "+f"(c[0]), "+f"(c[1]), "+f"(c[2]), "+f"(c[3])
      : "r"(a[0]), "r"(a[1]), "r"(a[2]), "r"(a[3]), "r"(b[0]), "r"(b[1]));
}
static __device__ __forceinline__ void split8(const float* f, uint4& H,
                                              uint4& L) {
  uint32_t h[4], l[4];
#pragma unroll
  for (int j = 0; j < 4; ++j) {
    __nv_bfloat16 h0 = __float2bfloat16(f[2 * j]);
    __nv_bfloat16 h1 = __float2bfloat16(f[2 * j + 1]);
    __nv_bfloat16 l0 = __float2bfloat16(f[2 * j] - __bfloat162float(h0));
    __nv_bfloat16 l1 = __float2bfloat16(f[2 * j + 1] - __bfloat162float(h1));
    h[j] = (uint32_t)__bfloat16_as_ushort(h0) |
           ((uint32_t)__bfloat16_as_ushort(h1) << 16);
    l[j] = (uint32_t)__bfloat16_as_ushort(l0) |
           ((uint32_t)__bfloat16_as_ushort(l1) << 16);
  }
  H = make_uint4(h[0], h[1], h[2], h[3]);
  L = make_uint4(l[0], l[1], l[2], l[3]);
}

// ---------------------------------------------------------------------------
// Pack: fp32 [rows,1024] -> SW128 bf16 hi/lo panels. grid (kb16, rb8, b16).
// which: 0 = enc->encP; 1 = dec->decP and ALSO copy dec into out[..., 0:1024]
// ---------------------------------------------------------------------------
__global__ __launch_bounds__(256) void conv_split_kernel(
    const float* __restrict__ src, float* __restrict__ out, int which) {
  uint4* dh = which ? g_decPh : g_encPh;
  uint4* dl = which ? g_decPl : g_encPl;
  const int kb = blockIdx.x, rb = blockIdx.y, b = blockIdx.z;
  const size_t panel = ((size_t)(b * 8 + rb) * 16 + kb) * PANEL_U4;
  const float* sp = src + ((size_t)b * 1024 + rb * 128) * 1024 + kb * 64;
#pragma unroll
  for (int it = 0; it < 4; ++it) {
    const int chunk = it * 256 + threadIdx.x;
    const int r = chunk >> 3, cc = chunk & 7;
    const float4* s4 =
        reinterpret_cast<const float4*>(sp + (size_t)r * 1024 + cc * 8);
    float4 x0 = s4[0], x1 = s4[1];
    float f[8] = {x0.x, x0.y, x0.z, x0.w, x1.x, x1.y, x1.z, x1.w};
    uint4 H, L;
    split8(f, H, L);
    const uint32_t off = swz((uint32_t)(r * 128 + cc * 16)) >> 4;
    dh[panel + off] = H;
    dl[panel + off] = L;
    if (which) {
      // fused concat copy: out[b, rb*128+r, kb*64 + cc*8 ..] = dec row
      float4* o4 = reinterpret_cast<float4*>(
          out + ((size_t)(b * 1024 + rb * 128 + r)) * 2048 + kb * 64 + cc * 8);
      o4[0] = x0;
      o4[1] = x1;
    }
  }
}

// transpose pack: enc [e,d] -> encT panels over [d-rowblk][e-kblk]
__global__ __launch_bounds__(256) void conv_split_T_kernel(
    const float* __restrict__ src) {
  const int eb = blockIdx.x, db = blockIdx.y, b = blockIdx.z;
  __shared__ float tile[64 * 132];
  const float* sp = src + ((size_t)b * 1024 + eb * 64) * 1024 + db * 128;
#pragma unroll
  for (int it = 0; it < 8; ++it) {
    const int idx = it * 256 + threadIdx.x;
    const int e = idx >> 5, c4 = idx & 31;
    float4 v = *reinterpret_cast<const float4*>(sp + (size_t)e * 1024 + c4 * 4);
    *reinterpret_cast<float4*>(tile + e * 132 + c4 * 4) = v;
  }
  __syncthreads();
  const size_t panel = ((size_t)(b * 8 + db) * 16 + eb) * PANEL_U4;
#pragma unroll
  for (int it = 0; it < 4; ++it) {
    const int chunk = it * 256 + threadIdx.x;
    const int d = chunk >> 3, ec = chunk & 7;
    float f[8];
#pragma unroll
    for (int j = 0; j < 8; ++j) f[j] = tile[(ec * 8 + j) * 132 + d];
    uint4 H, L;
    split8(f, H, L);
    const uint32_t off = swz((uint32_t)(d * 128 + ec * 16)) >> 4;
    g_encTh[panel + off] = H;
    g_encTl[panel + off] = L;
  }
}

// ---------------------------------------------------------------------------
// Softmax over e + transpose + bf16 hi/lo pack of attn^T [t,e]
// grid (tchunk=16, b=16), block (64,4)
// ---------------------------------------------------------------------------
__global__ __launch_bounds__(256) void softmax_pack_kernel() {
  const int b = blockIdx.y;
  const int t0 = blockIdx.x * 64;
  const int tx = threadIdx.x, ty = threadIdx.y;
  const int ltid = ty * 64 + tx;
  const float* Sb = g_S + (size_t)b * 1024 * 1024;
  __shared__ float sm[4][64], ss[4][64], Mv[64], Iv[64];
  __shared__ float tile[64 * 68];

  float m = -3.402823466e38f, s = 0.f;
  for (int e = ty; e < 1024; e += 4) {
    float v = Sb[(size_t)e * 1024 + t0 + tx];
    float mn = fmaxf(m, v);
    s = s * __expf(m - mn) + __expf(v - mn);
    m = mn;
  }
  sm[ty][tx] = m;
  ss[ty][tx] = s;
  __syncthreads();
  if (ty == 0) {
    float M = sm[0][tx], S = ss[0][tx];
#pragma unroll
    for (int i = 1; i < 4; ++i) {
      float mi = sm[i][tx], si = ss[i][tx];
      float mn = fmaxf(M, mi);
      S = S * __expf(M - mn) + si * __expf(mi - mn);
      M = mn;
    }
    Mv[tx] = M;
    Iv[tx] = 1.f / S;
  }
  __syncthreads();

  const int tb = t0 >> 7;
  const int tl0 = t0 & 127;
  for (int eb = 0; eb < 16; ++eb) {
#pragma unroll
    for (int it = 0; it < 4; ++it) {
      const int idx = it * 256 + ltid;
      const int e = idx >> 4, c4 = idx & 15;
      float4 v = *reinterpret_cast<const float4*>(
          Sb + (size_t)(eb * 64 + e) * 1024 + t0 + c4 * 4);
      const int t = c4 * 4;
      float4 p;
      p.x = __expf(v.x - Mv[t + 0]) * Iv[t + 0];
      p.y = __expf(v.y - Mv[t + 1]) * Iv[t + 1];
      p.z = __expf(v.z - Mv[t + 2]) * Iv[t + 2];
      p.w = __expf(v.w - Mv[t + 3]) * Iv[t + 3];
      *reinterpret_cast<float4*>(tile + e * 68 + c4 * 4) = p;
    }
    __syncthreads();
    const size_t panel = ((size_t)(b * 8 + tb) * 16 + eb) * PANEL_U4;
#pragma unroll
    for (int it = 0; it < 2; ++it) {
      const int chunk = it * 256 + ltid;
      const int tl = chunk >> 3, ec = chunk & 7;
      float f[8];
#pragma unroll
      for (int j = 0; j < 8; ++j) f[j] = tile[(ec * 8 + j) * 68 + tl];
      uint4 H, L;
      split8(f, H, L);
      const uint32_t off = swz((uint32_t)((tl0 + tl) * 128 + ec * 16)) >> 4;
      g_attTh[panel + off] = H;
      g_attTl[panel + off] = L;
    }
    __syncthreads();
  }
}

// ---------------------------------------------------------------------------
// HMMA GEMM: C tile 128(M) x 64(N) fp32, K=1024, bf16 hi/lo split (3 MMAs).
// grid (nbk=16, mbk=8, b=16), 256 threads (8 warps: 4 m x 2 n, warp 32x32),
// BK=64, 2-stage cp.async pipeline, 48KB/stage => 96KB => 2 CTAs/SM.
// which: 0 = GEMM1 (encP x decP -> g_S), 1 = GEMM2 (attT x encT -> out ctx)
// ---------------------------------------------------------------------------
__global__ __launch_bounds__(256, 2) void hmma_gemm_kernel(
    float* __restrict__ o, int which) {
  extern __shared__ __align__(16) char dsm[];
  const uint4 *Ah, *Al, *Bh, *Bl;
  float* C;
  int ldc, coff;
  size_t bstride;
  if (which == 0) {
    Ah = g_encPh; Al = g_encPl; Bh = g_decPh; Bl = g_decPl;
    C = g_S; ldc = 1024; coff = 0; bstride = (size_t)1024 * 1024;
  } else {
    Ah = g_attTh; Al = g_attTl; Bh = g_encTh; Bl = g_encTl;
    C = o; ldc = 2048; coff = 1024; bstride = (size_t)1024 * 2048;
  }

  const int tid = threadIdx.x;
  const int wid = tid >> 5, lane = tid & 31;
  const int wm = wid & 3, wn = wid >> 2;  // warp tile: rows wm*32, cols wn*32
  const int b = blockIdx.z, mbk = blockIdx.y, nbk = blockIdx.x;
  const size_t apan = ((size_t)(b * 8 + mbk)) * 16;
  const size_t bpan = ((size_t)(b * 8 + (nbk >> 1))) * 16;
  const int brow0 = (nbk & 1) * 64;  // which half of the 128-row B panel
  const uint32_t smem_base = smem_u32(dsm);

  // stage layout: Ah 0..16K, Al 16K..32K, Bh 32K..40K, Bl 40K..48K
  auto issue_chunk = [&](int c) {
    const uint32_t base = smem_base + (uint32_t)(c & 1) * 49152u;
    const uint4* a0 = Ah + (apan + c) * PANEL_U4;
    const uint4* a1 = Al + (apan + c) * PANEL_U4;
    const uint4* b0 = Bh + (bpan + c) * PANEL_U4;
    const uint4* b1 = Bl + (bpan + c) * PANEL_U4;
#pragma unroll
    for (int j = 0; j < 4; ++j) {  // A: 2048 uint4
      const int i = tid + j * 256;
      cp_async16(base + (uint32_t)i * 16u, a0 + i);
      cp_async16(base + 16384u + (uint32_t)i * 16u, a1 + i);
    }
#pragma unroll
    for (int j = 0; j < 2; ++j) {  // B: rows brow0..brow0+63 of panel
      const int lu = tid + j * 256;           // 0..511 (64 rows x 8 units)
      const int prow = brow0 + (lu >> 3), uin = lu & 7;
      cp_async16(base + 32768u + (uint32_t)lu * 16u, b0 + prow * 8 + uin);
      cp_async16(base + 40960u + (uint32_t)lu * 16u, b1 + prow * 8 + uin);
    }
    asm volatile("cp.async.commit_group;" ::: "memory");
  };

  float acc[2][4][4];
#pragma unroll
  for (int mt = 0; mt < 2; ++mt)
#pragma unroll
    for (int nt = 0; nt < 4; ++nt)
#pragma unroll
      for (int j = 0; j < 4; ++j) acc[mt][nt][j] = 0.f;

  issue_chunk(0);
  issue_chunk(1);

  const uint32_t a_row = (uint32_t)(wm * 32 + (lane & 15));
  const uint32_t a_koff = (lane & 16) ? 16u : 0u;
  const uint32_t b_row =
      (uint32_t)(wn * 32 + (lane & 7) + ((lane & 16) ? 8 : 0));
  const uint32_t b_koff = (lane & 8) ? 16u : 0u;

  for (int c = 0; c < 16; ++c) {
    asm volatile("cp.async.wait_group 1;" ::: "memory");
    __syncthreads();
    const uint32_t sb = smem_base + (uint32_t)(c & 1) * 49152u;
    const uint32_t Ah_b = sb, Al_b = sb + 16384u;
    const uint32_t Bh_b = sb + 32768u, Bl_b = sb + 40960u;

#pragma unroll
    for (int kk = 0; kk < 4; ++kk) {
      uint32_t ah[2][4], al[2][4];
#pragma unroll
      for (int mt = 0; mt < 2; ++mt) {
        const uint32_t byte = swz((a_row + (uint32_t)mt * 16u) * 128u +
                                  (uint32_t)kk * 32u + a_koff);
        ldsm4(ah[mt], Ah_b + byte);
        ldsm4(al[mt], Al_b + byte);
      }
      uint32_t bh[2][4], bl[2][4];
#pragma unroll
      for (int np = 0; np < 2; ++np) {
        const uint32_t byte = swz((b_row + (uint32_t)np * 16u) * 128u +
                                  (uint32_t)kk * 32u + b_koff);
        ldsm4(bh[np], Bh_b + byte);
        ldsm4(bl[np], Bl_b + byte);
      }
#pragma unroll
      for (int mt = 0; mt < 2; ++mt)
#pragma unroll
        for (int nt = 0; nt < 4; ++nt) {
          const uint32_t* B0 = &bh[nt >> 1][(nt & 1) * 2];
          const uint32_t* B1 = &bl[nt >> 1][(nt & 1) * 2];
          mma16816(acc[mt][nt], ah[mt], B0);
          mma16816(acc[mt][nt], ah[mt], B1);
          mma16816(acc[mt][nt], al[mt], B0);
        }
    }
    __syncthreads();
    if (c + 2 < 16) issue_chunk(c + 2);
  }

  float* Cb = C + (size_t)b * bstride + (size_t)(mbk * 128) * ldc + coff +
              nbk * 64;
  const int g = lane >> 2, tig = lane & 3;
#pragma unroll
  for (int mt = 0; mt < 2; ++mt)
#pragma unroll
    for (int nt = 0; nt < 4; ++nt) {
      const int row = wm * 32 + mt * 16 + g;
      const int col = wn * 32 + nt * 8 + tig * 2;
      *reinterpret_cast<float2*>(Cb + (size_t)row * ldc + col) =
          make_float2(acc[mt][nt][0], acc[mt][nt][1]);
      *reinterpret_cast<float2*>(Cb + (size_t)(row + 8) * ldc + col) =
          make_float2(acc[mt][nt][2], acc[mt][nt][3]);
    }
}

// ---------------------------------------------------------------------------
extern "C" void kernel_launch(void* const* d_in, const int* in_sizes, int n_in,
                              void* d_out, int out_size) {
  const float* enc = (const float*)d_in[0];
  const float* dec = (const float*)d_in[1];
  float* out = (float*)d_out;

  cudaFuncSetAttribute(hmma_gemm_kernel,
                       cudaFuncAttributeMaxDynamicSharedMemorySize, 98304);

  dim3 cg(16, 8, 16);
  conv_split_kernel<<<cg, 256>>>(enc, out, 0);
  conv_split_kernel<<<cg, 256>>>(dec, out, 1);  // also writes out[:, :1024]
  conv_split_T_kernel<<<cg, 256>>>(enc);

  dim3 gg(16, 8, 16);
  hmma_gemm_kernel<<<gg, 256, 98304>>>(out, 0);

  dim3 gs(16, 16);
  softmax_pack_kernel<<<gs, dim3(64, 4)>>>();

  hmma_gemm_kernel<<<gg, 256, 98304>>>(out, 1);
}

// round 6
// speedup vs baseline: 2.5567x; 1.0212x over previous
#include <cuda_runtime.h>
#include <cuda_bf16.h>
#include <cstdint>

// B=16, Te=1024, Td=1024, D=1024
//   S[b,e,t]   = enc[b,e,:] . dec[b,t,:]          (GEMM1)
//   A          = softmax_e(S)
//   ctx[b,t,d] = sum_e A[e,t] enc[e,d]            (GEMM2: A from attT panels,
//                                                  B from encP via ldmatrix.trans)
//   out        = concat(dec, ctx)                 [B, Td, 2048]
//
// Tensor cores via mma.sync bf16 hi/lo split: a*b ~= ah*bh + ah*bl + al*bh

#define PANEL_U4 1024  // one 128x64-bf16 SW128 panel = 16KB = 1024 uint4
#define NPANEL 2048    // 16 b * 8 rowblk * 16 kblk

__device__ float g_S[(size_t)16 * 1024 * 1024];  // fp32 scores
__device__ uint4 g_encPh[NPANEL * PANEL_U4], g_encPl[NPANEL * PANEL_U4];  // enc [e,d]
__device__ uint4 g_decPh[NPANEL * PANEL_U4], g_decPl[NPANEL * PANEL_U4];  // dec [t,d]
__device__ uint4 g_attTh[NPANEL * PANEL_U4], g_attTl[NPANEL * PANEL_U4];  // attn^T [t,e]

// ---------------------------------------------------------------------------
static __device__ __forceinline__ uint32_t smem_u32(const void* p) {
  uint32_t a;
  asm("{ .reg .u64 t; cvta.to.shared.u64 t, %1; cvt.u32.u64 %0, t; }"
      : "=r"(a) : "l"(p));
  return a;
}
static __device__ __forceinline__ uint32_t swz(uint32_t x) {
  return x ^ ((x >> 3) & 0x70);
}
static __device__ __forceinline__ void cp_async16(uint32_t dst,
                                                  const void* src) {
  asm volatile("cp.async.cg.shared.global [%0], [%1], 16;"
               :: "r"(dst), "l"(src) : "memory");
}
static __device__ __forceinline__ void ldsm4(uint32_t* r, uint32_t addr) {
  asm volatile(
      "ldmatrix.sync.aligned.m8n8.x4.shared.b16 {%0,%1,%2,%3}, [%4];"
      : "=r"(r[0]), "=r"(r[1]), "=r"(r[2]), "=r"(r[3])
      : "r"(addr));
}
static __device__ __forceinline__ void ldsm4t(uint32_t* r, uint32_t addr) {
  asm volatile(
      "ldmatrix.sync.aligned.m8n8.x4.trans.shared.b16 {%0,%1,%2,%3}, [%4];"
      : "=r"(r[0]), "=r"(r[1]), "=r"(r[2]), "=r"(r[3])
      : "r"(addr));
}
static __device__ __forceinline__ void mma16816(float* c, const uint32_t* a,
                                                const uint32_t* b) {
  asm volatile(
      "mma.sync.aligned.m16n8k16.row.col.f32.bf16.bf16.f32 "
      "{%0,%1,%2,%3}, {%4,%5,%6,%7}, {%8,%9}, {%0,%1,%2,%3};"
      : "+f"(c[0]), "+f"(c[1]), "+f"(c[2]), "+f"(c[3])
      : "r"(a[0]), "r"(a[1]), "r"(a[2]), "r"(a[3]), "r"(b[0]), "r"(b[1]));
}
static __device__ __forceinline__ uint32_t cvt_bf16x2(float hi, float lo) {
  uint32_t r;
  asm("cvt.rn.bf16x2.f32 %0, %1, %2;" : "=r"(r) : "f"(hi), "f"(lo));
  return r;
}
// hi/lo split, 2 elems/cvt; bf16->f32 via exact bit-shift
static __device__ __forceinline__ void split8(const float* f, uint4& H,
                                              uint4& L) {
  uint32_t h[4], l[4];
#pragma unroll
  for (int j = 0; j < 4; ++j) {
    const float f0 = f[2 * j], f1 = f[2 * j + 1];
    const uint32_t hu = cvt_bf16x2(f1, f0);          // lo half = f0
    const float fh0 = __uint_as_float(hu << 16);
    const float fh1 = __uint_as_float(hu & 0xFFFF0000u);
    h[j] = hu;
    l[j] = cvt_bf16x2(f1 - fh1, f0 - fh0);
  }
  H = make_uint4(h[0], h[1], h[2], h[3]);
  L = make_uint4(l[0], l[1], l[2], l[3]);
}

// ---------------------------------------------------------------------------
// Pack: fp32 [rows,1024] -> SW128 bf16 hi/lo panels. grid (kb16, rb8, b16).
// which: 0 = enc->encP; 1 = dec->decP and ALSO copy dec into out[..., 0:1024]
// ---------------------------------------------------------------------------
__global__ __launch_bounds__(256) void conv_split_kernel(
    const float* __restrict__ src, float* __restrict__ out, int which) {
  uint4* dh = which ? g_decPh : g_encPh;
  uint4* dl = which ? g_decPl : g_encPl;
  const int kb = blockIdx.x, rb = blockIdx.y, b = blockIdx.z;
  const size_t panel = ((size_t)(b * 8 + rb) * 16 + kb) * PANEL_U4;
  const float* sp = src + ((size_t)b * 1024 + rb * 128) * 1024 + kb * 64;
#pragma unroll
  for (int it = 0; it < 4; ++it) {
    const int chunk = it * 256 + threadIdx.x;
    const int r = chunk >> 3, cc = chunk & 7;
    const float4* s4 =
        reinterpret_cast<const float4*>(sp + (size_t)r * 1024 + cc * 8);
    float4 x0 = s4[0], x1 = s4[1];
    float f[8] = {x0.x, x0.y, x0.z, x0.w, x1.x, x1.y, x1.z, x1.w};
    uint4 H, L;
    split8(f, H, L);
    const uint32_t off = swz((uint32_t)(r * 128 + cc * 16)) >> 4;
    dh[panel + off] = H;
    dl[panel + off] = L;
    if (which) {
      float4* o4 = reinterpret_cast<float4*>(
          out + ((size_t)(b * 1024 + rb * 128 + r)) * 2048 + kb * 64 + cc * 8);
      o4[0] = x0;
      o4[1] = x1;
    }
  }
}

// ---------------------------------------------------------------------------
// Softmax over e + transpose + bf16 hi/lo pack of attn^T [t,e]
// grid (tchunk=16, b=16), block (64,4)
// ---------------------------------------------------------------------------
__global__ __launch_bounds__(256) void softmax_pack_kernel() {
  const int b = blockIdx.y;
  const int t0 = blockIdx.x * 64;
  const int tx = threadIdx.x, ty = threadIdx.y;
  const int ltid = ty * 64 + tx;
  const float* Sb = g_S + (size_t)b * 1024 * 1024;
  __shared__ float sm[4][64], ss[4][64], Mv[64], Iv[64];
  __shared__ float tile[64 * 68];

  float m = -3.402823466e38f, s = 0.f;
  for (int e = ty; e < 1024; e += 4) {
    float v = Sb[(size_t)e * 1024 + t0 + tx];
    float mn = fmaxf(m, v);
    s = s * __expf(m - mn) + __expf(v - mn);
    m = mn;
  }
  sm[ty][tx] = m;
  ss[ty][tx] = s;
  __syncthreads();
  if (ty == 0) {
    float M = sm[0][tx], S = ss[0][tx];
#pragma unroll
    for (int i = 1; i < 4; ++i) {
      float mi = sm[i][tx], si = ss[i][tx];
      float mn = fmaxf(M, mi);
      S = S * __expf(M - mn) + si * __expf(mi - mn);
      M = mn;
    }
    Mv[tx] = M;
    Iv[tx] = 1.f / S;
  }
  __syncthreads();

  const int tb = t0 >> 7;
  const int tl0 = t0 & 127;
  for (int eb = 0; eb < 16; ++eb) {
#pragma unroll
    for (int it = 0; it < 4; ++it) {
      const int idx = it * 256 + ltid;
      const int e = idx >> 4, c4 = idx & 15;
      float4 v = *reinterpret_cast<const float4*>(
          Sb + (size_t)(eb * 64 + e) * 1024 + t0 + c4 * 4);
      const int t = c4 * 4;
      float4 p;
      p.x = __expf(v.x - Mv[t + 0]) * Iv[t + 0];
      p.y = __expf(v.y - Mv[t + 1]) * Iv[t + 1];
      p.z = __expf(v.z - Mv[t + 2]) * Iv[t + 2];
      p.w = __expf(v.w - Mv[t + 3]) * Iv[t + 3];
      *reinterpret_cast<float4*>(tile + e * 68 + c4 * 4) = p;
    }
    __syncthreads();
    const size_t panel = ((size_t)(b * 8 + tb) * 16 + eb) * PANEL_U4;
#pragma unroll
    for (int it = 0; it < 2; ++it) {
      const int chunk = it * 256 + ltid;
      const int tl = chunk >> 3, ec = chunk & 7;
      float f[8];
#pragma unroll
      for (int j = 0; j < 8; ++j) f[j] = tile[(ec * 8 + j) * 68 + tl];
      uint4 H, L;
      split8(f, H, L);
      const uint32_t off = swz((uint32_t)((tl0 + tl) * 128 + ec * 16)) >> 4;
      g_attTh[panel + off] = H;
      g_attTl[panel + off] = L;
    }
    __syncthreads();
  }
}

// ---------------------------------------------------------------------------
// HMMA GEMM: C tile 128(M) x 64(N) fp32, K=1024, bf16 hi/lo split (3 MMAs).
// grid (nbk=16, mbk=8, b=16), 256 threads (8 warps: 4 m x 2 n, warp 32x32),
// BK=64, 2-stage cp.async pipeline, 48KB/stage => 96KB => 2 CTAs/SM.
// WHICH=0: GEMM1 encP x decP -> g_S        (B non-trans, [n,k]-major panels)
// WHICH=1: GEMM2 attT x encP -> out ctx    (B via ldmatrix.trans, [k,n]-major)
// ---------------------------------------------------------------------------
template <int WHICH>
__global__ __launch_bounds__(256, 2) void hmma_gemm_kernel(
    float* __restrict__ o) {
  extern __shared__ __align__(16) char dsm[];
  const uint4* Ah = WHICH ? g_attTh : g_encPh;
  const uint4* Al = WHICH ? g_attTl : g_encPl;
  const uint4* Bh = WHICH ? g_encPh : g_decPh;
  const uint4* Bl = WHICH ? g_encPl : g_decPl;
  float* C;
  int ldc, coff;
  size_t bstride;
  if (WHICH == 0) {
    C = g_S; ldc = 1024; coff = 0; bstride = (size_t)1024 * 1024;
  } else {
    C = o; ldc = 2048; coff = 1024; bstride = (size_t)1024 * 2048;
  }

  const int tid = threadIdx.x;
  const int wid = tid >> 5, lane = tid & 31;
  const int wm = wid & 3, wn = wid >> 2;  // warp tile: rows wm*32, cols wn*32
  const int b = blockIdx.z, mbk = blockIdx.y, nbk = blockIdx.x;
  const size_t apan = ((size_t)(b * 8 + mbk)) * 16;
  const uint32_t smem_base = smem_u32(dsm);

  // stage layout: Ah 0..16K, Al 16K..32K, Bh 32K..40K, Bl 40K..48K
  auto issue_chunk = [&](int c) {
    const uint32_t base = smem_base + (uint32_t)(c & 1) * 49152u;
    const uint4* a0 = Ah + (apan + c) * PANEL_U4;
    const uint4* a1 = Al + (apan + c) * PANEL_U4;
    size_t bpan;
    int brow0;
    if (WHICH == 0) {  // B = dec [t,d]: panel rowblk = t (nbk), kblk = d (c)
      bpan = ((size_t)(b * 8 + (nbk >> 1)) * 16 + c) * PANEL_U4;
      brow0 = (nbk & 1) * 64;
    } else {  // B = enc [e,d]: panel rowblk = e (c), kblk = d (nbk)
      bpan = ((size_t)(b * 8 + (c >> 1)) * 16 + nbk) * PANEL_U4;
      brow0 = (c & 1) * 64;
    }
    const uint4* b0 = Bh + bpan;
    const uint4* b1 = Bl + bpan;
#pragma unroll
    for (int j = 0; j < 4; ++j) {  // A: 2048 uint4
      const int i = tid + j * 256;
      cp_async16(base + (uint32_t)i * 16u, a0 + i);
      cp_async16(base + 16384u + (uint32_t)i * 16u, a1 + i);
    }
#pragma unroll
    for (int j = 0; j < 2; ++j) {  // B: 64 rows of the 128-row panel
      const int lu = tid + j * 256;  // 0..511
      const int prow = brow0 + (lu >> 3), uin = lu & 7;
      cp_async16(base + 32768u + (uint32_t)lu * 16u, b0 + prow * 8 + uin);
      cp_async16(base + 40960u + (uint32_t)lu * 16u, b1 + prow * 8 + uin);
    }
    asm volatile("cp.async.commit_group;" ::: "memory");
  };

  float acc[2][4][4];
#pragma unroll
  for (int mt = 0; mt < 2; ++mt)
#pragma unroll
    for (int nt = 0; nt < 4; ++nt)
#pragma unroll
      for (int j = 0; j < 4; ++j) acc[mt][nt][j] = 0.f;

  issue_chunk(0);
  issue_chunk(1);

  const uint32_t a_row = (uint32_t)(wm * 32 + (lane & 15));
  const uint32_t a_koff = (lane & 16) ? 16u : 0u;
  // B addressing:
  //  WHICH==0 (non-trans): lane -> n-row of [n,k] tile
  const uint32_t b_row =
      (uint32_t)(wn * 32 + (lane & 7) + ((lane & 16) ? 8 : 0));
  const uint32_t b_koff = (lane & 8) ? 16u : 0u;
  //  WHICH==1 (trans): lane -> k-row of [k,n] tile
  const uint32_t bt_krow = (uint32_t)(lane & 15);
  const uint32_t bt_coff = (uint32_t)(wn * 32 + ((lane & 16) ? 8 : 0)) * 2u;

  for (int c = 0; c < 16; ++c) {
    asm volatile("cp.async.wait_group 1;" ::: "memory");
    __syncthreads();
    const uint32_t sb = smem_base + (uint32_t)(c & 1) * 49152u;
    const uint32_t Ah_b = sb, Al_b = sb + 16384u;
    const uint32_t Bh_b = sb + 32768u, Bl_b = sb + 40960u;

#pragma unroll
    for (int kk = 0; kk < 4; ++kk) {
      uint32_t ah[2][4], al[2][4];
#pragma unroll
      for (int mt = 0; mt < 2; ++mt) {
        const uint32_t byte = swz((a_row + (uint32_t)mt * 16u) * 128u +
                                  (uint32_t)kk * 32u + a_koff);
        ldsm4(ah[mt], Ah_b + byte);
        ldsm4(al[mt], Al_b + byte);
      }
      uint32_t bh[2][4], bl[2][4];
#pragma unroll
      for (int np = 0; np < 2; ++np) {
        if (WHICH == 0) {
          const uint32_t byte = swz((b_row + (uint32_t)np * 16u) * 128u +
                                    (uint32_t)kk * 32u + b_koff);
          ldsm4(bh[np], Bh_b + byte);
          ldsm4(bl[np], Bl_b + byte);
        } else {
          const uint32_t byte =
              swz(((uint32_t)kk * 16u + bt_krow) * 128u + bt_coff +
                  (uint32_t)np * 32u);
          ldsm4t(bh[np], Bh_b + byte);
          ldsm4t(bl[np], Bl_b + byte);
        }
      }
#pragma unroll
      for (int mt = 0; mt < 2; ++mt)
#pragma unroll
        for (int nt = 0; nt < 4; ++nt) {
          const uint32_t* B0 = &bh[nt >> 1][(nt & 1) * 2];
          const uint32_t* B1 = &bl[nt >> 1][(nt & 1) * 2];
          mma16816(acc[mt][nt], ah[mt], B0);
          mma16816(acc[mt][nt], ah[mt], B1);
          mma16816(acc[mt][nt], al[mt], B0);
        }
    }
    __syncthreads();
    if (c + 2 < 16) issue_chunk(c + 2);
  }

  float* Cb = C + (size_t)b * bstride + (size_t)(mbk * 128) * ldc + coff +
              nbk * 64;
  const int g = lane >> 2, tig = lane & 3;
#pragma unroll
  for (int mt = 0; mt < 2; ++mt)
#pragma unroll
    for (int nt = 0; nt < 4; ++nt) {
      const int row = wm * 32 + mt * 16 + g;
      const int col = wn * 32 + nt * 8 + tig * 2;
      *reinterpret_cast<float2*>(Cb + (size_t)row * ldc + col) =
          make_float2(acc[mt][nt][0], acc[mt][nt][1]);
      *reinterpret_cast<float2*>(Cb + (size_t)(row + 8) * ldc + col) =
          make_float2(acc[mt][nt][2], acc[mt][nt][3]);
    }
}

// ---------------------------------------------------------------------------
extern "C" void kernel_launch(void* const* d_in, const int* in_sizes, int n_in,
                              void* d_out, int out_size) {
  const float* enc = (const float*)d_in[0];
  const float* dec = (const float*)d_in[1];
  float* out = (float*)d_out;

  cudaFuncSetAttribute(hmma_gemm_kernel<0>,
                       cudaFuncAttributeMaxDynamicSharedMemorySize, 98304);
  cudaFuncSetAttribute(hmma_gemm_kernel<1>,
                       cudaFuncAttributeMaxDynamicSharedMemorySize, 98304);

  dim3 cg(16, 8, 16);
  conv_split_kernel<<<cg, 256>>>(enc, out, 0);
  conv_split_kernel<<<cg, 256>>>(dec, out, 1);  // also writes out[:, :1024]

  dim3 gg(16, 8, 16);
  hmma_gemm_kernel<0><<<gg, 256, 98304>>>(out);

  dim3 gs(16, 16);
  softmax_pack_kernel<<<gs, dim3(64, 4)>>>();

  hmma_gemm_kernel<1><<<gg, 256, 98304>>>(out);
}

// round 7
// speedup vs baseline: 2.6486x; 1.0359x over previous
#include <cuda_runtime.h>
#include <cuda_bf16.h>
#include <cstdint>

// B=16, Te=1024, Td=1024, D=1024
//   S[b,e,t]   = enc[b,e,:] . dec[b,t,:]          (GEMM1)
//   A          = softmax_e(S)
//   ctx[b,t,d] = sum_e A[e,t] enc[e,d]            (GEMM2: A from attT panels,
//                                                  B from encP via ldmatrix.trans)
//   out        = concat(dec, ctx)                 [B, Td, 2048]
//
// Tensor cores via mma.sync bf16 hi/lo split: a*b ~= ah*bh + ah*bl + al*bh

#define PANEL_U4 1024  // one 128x64-bf16 SW128 panel = 16KB = 1024 uint4
#define NPANEL 2048    // 16 b * 8 rowblk * 16 kblk

__device__ float g_S[(size_t)16 * 1024 * 1024];  // fp32 scores
__device__ uint4 g_encPh[NPANEL * PANEL_U4], g_encPl[NPANEL * PANEL_U4];  // enc [e,d]
__device__ uint4 g_decPh[NPANEL * PANEL_U4], g_decPl[NPANEL * PANEL_U4];  // dec [t,d]
__device__ uint4 g_attTh[NPANEL * PANEL_U4], g_attTl[NPANEL * PANEL_U4];  // attn^T [t,e]

// ---------------------------------------------------------------------------
static __device__ __forceinline__ uint32_t smem_u32(const void* p) {
  uint32_t a;
  asm("{ .reg .u64 t; cvta.to.shared.u64 t, %1; cvt.u32.u64 %0, t; }"
      : "=r"(a) : "l"(p));
  return a;
}
static __device__ __forceinline__ uint32_t swz(uint32_t x) {
  return x ^ ((x >> 3) & 0x70);
}
static __device__ __forceinline__ void cp_async16(uint32_t dst,
                                                  const void* src) {
  asm volatile("cp.async.cg.shared.global [%0], [%1], 16;"
               :: "r"(dst), "l"(src) : "memory");
}
static __device__ __forceinline__ void ldsm4(uint32_t* r, uint32_t addr) {
  asm volatile(
      "ldmatrix.sync.aligned.m8n8.x4.shared.b16 {%0,%1,%2,%3}, [%4];"
      : "=r"(r[0]), "=r"(r[1]), "=r"(r[2]), "=r"(r[3])
      : "r"(addr));
}
static __device__ __forceinline__ void ldsm4t(uint32_t* r, uint32_t addr) {
  asm volatile(
      "ldmatrix.sync.aligned.m8n8.x4.trans.shared.b16 {%0,%1,%2,%3}, [%4];"
      : "=r"(r[0]), "=r"(r[1]), "=r"(r[2]), "=r"(r[3])
      : "r"(addr));
}
static __device__ __forceinline__ void mma16816(float* c, const uint32_t* a,
                                                const uint32_t* b) {
  asm volatile(
      "mma.sync.aligned.m16n8k16.row.col.f32.bf16.bf16.f32 "
      "{%0,%1,%2,%3}, {%4,%5,%6,%7}, {%8,%9}, {%0,%1,%2,%3};"
      : "+f"(c[0]), "+f"(c[1]), "+f"(c[2]), "+f"(c[3])
      : "r"(a[0]), "r"(a[1]), "r"(a[2]), "r"(a[3]), "r"(b[0]), "r"(b[1]));
}
static __device__ __forceinline__ uint32_t cvt_bf16x2(float hi, float lo) {
  uint32_t r;
  asm("cvt.rn.bf16x2.f32 %0, %1, %2;" : "=r"(r) : "f"(hi), "f"(lo));
  return r;
}
// hi/lo split, 2 elems/cvt; bf16->f32 via exact bit-shift
static __device__ __forceinline__ void split8(const float* f, uint4& H,
                                              uint4& L) {
  uint32_t h[4], l[4];
#pragma unroll
  for (int j = 0; j < 4; ++j) {
    const float f0 = f[2 * j], f1 = f[2 * j + 1];
    const uint32_t hu = cvt_bf16x2(f1, f0);  // lo half = f0
    const float fh0 = __uint_as_float(hu << 16);
    const float fh1 = __uint_as_float(hu & 0xFFFF0000u);
    h[j] = hu;
    l[j] = cvt_bf16x2(f1 - fh1, f0 - fh0);
  }
  H = make_uint4(h[0], h[1], h[2], h[3]);
  L = make_uint4(l[0], l[1], l[2], l[3]);
}

// ---------------------------------------------------------------------------
// Pack: fp32 [rows,1024] -> SW128 bf16 hi/lo panels. grid (kb16, rb8, b16).
// which: 0 = enc->encP; 1 = dec->decP and ALSO copy dec into out[..., 0:1024]
// ---------------------------------------------------------------------------
__global__ __launch_bounds__(256) void conv_split_kernel(
    const float* __restrict__ src, float* __restrict__ out, int which) {
  uint4* dh = which ? g_decPh : g_encPh;
  uint4* dl = which ? g_decPl : g_encPl;
  const int kb = blockIdx.x, rb = blockIdx.y, b = blockIdx.z;
  const size_t panel = ((size_t)(b * 8 + rb) * 16 + kb) * PANEL_U4;
  const float* sp = src + ((size_t)b * 1024 + rb * 128) * 1024 + kb * 64;
#pragma unroll
  for (int it = 0; it < 4; ++it) {
    const int chunk = it * 256 + threadIdx.x;
    const int r = chunk >> 3, cc = chunk & 7;
    const float4* s4 =
        reinterpret_cast<const float4*>(sp + (size_t)r * 1024 + cc * 8);
    float4 x0 = s4[0], x1 = s4[1];
    float f[8] = {x0.x, x0.y, x0.z, x0.w, x1.x, x1.y, x1.z, x1.w};
    uint4 H, L;
    split8(f, H, L);
    const uint32_t off = swz((uint32_t)(r * 128 + cc * 16)) >> 4;
    dh[panel + off] = H;
    dl[panel + off] = L;
    if (which) {
      float4* o4 = reinterpret_cast<float4*>(
          out + ((size_t)(b * 1024 + rb * 128 + r)) * 2048 + kb * 64 + cc * 8);
      o4[0] = x0;
      o4[1] = x1;
    }
  }
}

// ---------------------------------------------------------------------------
// Softmax over e + transpose + bf16 hi/lo pack of attn^T [t,e].
// One CTA per (b, 32 t-cols): stage full 1024x32 score tile in smem,
// pass1 max (no exp), pass2 exp once + sum, pass3 scale+transpose+pack.
// grid (tchunk=32, b=16), block (32, 16) = 512 threads.
// ---------------------------------------------------------------------------
#define SMX_STRIDE 33
__global__ __launch_bounds__(512) void softmax_pack_kernel() {
  extern __shared__ __align__(16) float tile[];  // [1024][33]
  __shared__ float sred[16][32], Mv[32], Iv[32];

  const int b = blockIdx.y;
  const int t0 = blockIdx.x * 32;
  const int tx = threadIdx.x;  // t-col 0..31
  const int ty = threadIdx.y;  // e-lane 0..15
  const int ltid = ty * 32 + tx;
  const float* Sb = g_S + (size_t)b * 1024 * 1024 + t0;

  // pass 1: load into smem + per-thread max (no exp)
  float m = -3.402823466e38f;
#pragma unroll 8
  for (int e = ty; e < 1024; e += 16) {
    const float v = Sb[(size_t)e * 1024 + tx];
    tile[e * SMX_STRIDE + tx] = v;
    m = fmaxf(m, v);
  }
  sred[ty][tx] = m;
  __syncthreads();
  if (ty == 0) {
    float M = sred[0][tx];
#pragma unroll
    for (int i = 1; i < 16; ++i) M = fmaxf(M, sred[i][tx]);
    Mv[tx] = M;
  }
  __syncthreads();

  // pass 2: exp once into smem + per-thread sum
  const float M = Mv[tx];
  float s = 0.f;
#pragma unroll 8
  for (int e = ty; e < 1024; e += 16) {
    const float p = __expf(tile[e * SMX_STRIDE + tx] - M);
    tile[e * SMX_STRIDE + tx] = p;
    s += p;
  }
  sred[ty][tx] = s;
  __syncthreads();
  if (ty == 0) {
    float S = sred[0][tx];
#pragma unroll
    for (int i = 1; i < 16; ++i) S += sred[i][tx];
    Iv[tx] = 1.f / S;
  }
  __syncthreads();

  // pass 3: scale + transpose + hi/lo pack (read-only smem, no syncs)
  const int tb = t0 >> 7;          // which 128-row panel block
  const int tl0 = t0 & 127;        // row offset within panel
  const int ebh = ltid >> 8;       // 0..1: which eb of the pair
  const int chunk = ltid & 255;    // 256 tasks: 32 t-rows x 8 ec
  const int tl = chunk >> 3, ec = chunk & 7;
  const float inv = Iv[tl];
#pragma unroll
  for (int ebp = 0; ebp < 8; ++ebp) {
    const int eb = ebp * 2 + ebh;
    float f[8];
#pragma unroll
    for (int j = 0; j < 8; ++j)
      f[j] = tile[(eb * 64 + ec * 8 + j) * SMX_STRIDE + tl] * inv;
    uint4 H, L;
    split8(f, H, L);
    const size_t panel = ((size_t)(b * 8 + tb) * 16 + eb) * PANEL_U4;
    const uint32_t off = swz((uint32_t)((tl0 + tl) * 128 + ec * 16)) >> 4;
    g_attTh[panel + off] = H;
    g_attTl[panel + off] = L;
  }
}

// ---------------------------------------------------------------------------
// HMMA GEMM: C tile 128(M) x 64(N) fp32, K=1024, bf16 hi/lo split (3 MMAs).
// grid (nbk=16, mbk=8, b=16), 256 threads (8 warps: 4 m x 2 n, warp 32x32),
// BK=64, 2-stage cp.async pipeline, 48KB/stage => 96KB => 2 CTAs/SM.
// WHICH=0: GEMM1 encP x decP -> g_S        (B non-trans, [n,k]-major panels)
// WHICH=1: GEMM2 attT x encP -> out ctx    (B via ldmatrix.trans, [k,n]-major)
// ---------------------------------------------------------------------------
template <int WHICH>
__global__ __launch_bounds__(256, 2) void hmma_gemm_kernel(
    float* __restrict__ o) {
  extern __shared__ __align__(16) char dsm[];
  const uint4* Ah = WHICH ? g_attTh : g_encPh;
  const uint4* Al = WHICH ? g_attTl : g_encPl;
  const uint4* Bh = WHICH ? g_encPh : g_decPh;
  const uint4* Bl = WHICH ? g_encPl : g_decPl;
  float* C;
  int ldc, coff;
  size_t bstride;
  if (WHICH == 0) {
    C = g_S; ldc = 1024; coff = 0; bstride = (size_t)1024 * 1024;
  } else {
    C = o; ldc = 2048; coff = 1024; bstride = (size_t)1024 * 2048;
  }

  const int tid = threadIdx.x;
  const int wid = tid >> 5, lane = tid & 31;
  const int wm = wid & 3, wn = wid >> 2;  // warp tile: rows wm*32, cols wn*32
  const int b = blockIdx.z, mbk = blockIdx.y, nbk = blockIdx.x;
  const size_t apan = ((size_t)(b * 8 + mbk)) * 16;
  const uint32_t smem_base = smem_u32(dsm);

  // stage layout: Ah 0..16K, Al 16K..32K, Bh 32K..40K, Bl 40K..48K
  auto issue_chunk = [&](int c) {
    const uint32_t base = smem_base + (uint32_t)(c & 1) * 49152u;
    const uint4* a0 = Ah + (apan + c) * PANEL_U4;
    const uint4* a1 = Al + (apan + c) * PANEL_U4;
    size_t bpan;
    int brow0;
    if (WHICH == 0) {  // B = dec [t,d]: panel rowblk = t (nbk), kblk = d (c)
      bpan = ((size_t)(b * 8 + (nbk >> 1)) * 16 + c) * PANEL_U4;
      brow0 = (nbk & 1) * 64;
    } else {  // B = enc [e,d]: panel rowblk = e (c), kblk = d (nbk)
      bpan = ((size_t)(b * 8 + (c >> 1)) * 16 + nbk) * PANEL_U4;
      brow0 = (c & 1) * 64;
    }
    const uint4* b0 = Bh + bpan;
    const uint4* b1 = Bl + bpan;
#pragma unroll
    for (int j = 0; j < 4; ++j) {  // A: 2048 uint4
      const int i = tid + j * 256;
      cp_async16(base + (uint32_t)i * 16u, a0 + i);
      cp_async16(base + 16384u + (uint32_t)i * 16u, a1 + i);
    }
#pragma unroll
    for (int j = 0; j < 2; ++j) {  // B: 64 rows of the 128-row panel
      const int lu = tid + j * 256;  // 0..511
      const int prow = brow0 + (lu >> 3), uin = lu & 7;
      cp_async16(base + 32768u + (uint32_t)lu * 16u, b0 + prow * 8 + uin);
      cp_async16(base + 40960u + (uint32_t)lu * 16u, b1 + prow * 8 + uin);
    }
    asm volatile("cp.async.commit_group;" ::: "memory");
  };

  float acc[2][4][4];
#pragma unroll
  for (int mt = 0; mt < 2; ++mt)
#pragma unroll
    for (int nt = 0; nt < 4; ++nt)
#pragma unroll
      for (int j = 0; j < 4; ++j) acc[mt][nt][j] = 0.f;

  issue_chunk(0);
  issue_chunk(1);

  const uint32_t a_row = (uint32_t)(wm * 32 + (lane & 15));
  const uint32_t a_koff = (lane & 16) ? 16u : 0u;
  const uint32_t b_row =
      (uint32_t)(wn * 32 + (lane & 7) + ((lane & 16) ? 8 : 0));
  const uint32_t b_koff = (lane & 8) ? 16u : 0u;
  const uint32_t bt_krow = (uint32_t)(lane & 15);
  const uint32_t bt_coff = (uint32_t)(wn * 32 + ((lane & 16) ? 8 : 0)) * 2u;

  for (int c = 0; c < 16; ++c) {
    asm volatile("cp.async.wait_group 1;" ::: "memory");
    __syncthreads();
    const uint32_t sb = smem_base + (uint32_t)(c & 1) * 49152u;
    const uint32_t Ah_b = sb, Al_b = sb + 16384u;
    const uint32_t Bh_b = sb + 32768u, Bl_b = sb + 40960u;

#pragma unroll
    for (int kk = 0; kk < 4; ++kk) {
      uint32_t ah[2][4], al[2][4];
#pragma unroll
      for (int mt = 0; mt < 2; ++mt) {
        const uint32_t byte = swz((a_row + (uint32_t)mt * 16u) * 128u +
                                  (uint32_t)kk * 32u + a_koff);
        ldsm4(ah[mt], Ah_b + byte);
        ldsm4(al[mt], Al_b + byte);
      }
      uint32_t bh[2][4], bl[2][4];
#pragma unroll
      for (int np = 0; np < 2; ++np) {
        if (WHICH == 0) {
          const uint32_t byte = swz((b_row + (uint32_t)np * 16u) * 128u +
                                    (uint32_t)kk * 32u + b_koff);
          ldsm4(bh[np], Bh_b + byte);
          ldsm4(bl[np], Bl_b + byte);
        } else {
          const uint32_t byte =
              swz(((uint32_t)kk * 16u + bt_krow) * 128u + bt_coff +
                  (uint32_t)np * 32u);
          ldsm4t(bh[np], Bh_b + byte);
          ldsm4t(bl[np], Bl_b + byte);
        }
      }
#pragma unroll
      for (int mt = 0; mt < 2; ++mt)
#pragma unroll
        for (int nt = 0; nt < 4; ++nt) {
          const uint32_t* B0 = &bh[nt >> 1][(nt & 1) * 2];
          const uint32_t* B1 = &bl[nt >> 1][(nt & 1) * 2];
          mma16816(acc[mt][nt], ah[mt], B0);
          mma16816(acc[mt][nt], ah[mt], B1);
          mma16816(acc[mt][nt], al[mt], B0);
        }
    }
    __syncthreads();
    if (c + 2 < 16) issue_chunk(c + 2);
  }

  float* Cb = C + (size_t)b * bstride + (size_t)(mbk * 128) * ldc + coff +
              nbk * 64;
  const int g = lane >> 2, tig = lane & 3;
#pragma unroll
  for (int mt = 0; mt < 2; ++mt)
#pragma unroll
    for (int nt = 0; nt < 4; ++nt) {
      const int row = wm * 32 + mt * 16 + g;
      const int col = wn * 32 + nt * 8 + tig * 2;
      *reinterpret_cast<float2*>(Cb + (size_t)row * ldc + col) =
          make_float2(acc[mt][nt][0], acc[mt][nt][1]);
      *reinterpret_cast<float2*>(Cb + (size_t)(row + 8) * ldc + col) =
          make_float2(acc[mt][nt][2], acc[mt][nt][3]);
    }
}

// ---------------------------------------------------------------------------
extern "C" void kernel_launch(void* const* d_in, const int* in_sizes, int n_in,
                              void* d_out, int out_size) {
  const float* enc = (const float*)d_in[0];
  const float* dec = (const float*)d_in[1];
  float* out = (float*)d_out;

  cudaFuncSetAttribute(hmma_gemm_kernel<0>,
                       cudaFuncAttributeMaxDynamicSharedMemorySize, 98304);
  cudaFuncSetAttribute(hmma_gemm_kernel<1>,
                       cudaFuncAttributeMaxDynamicSharedMemorySize, 98304);
  const int SMX_SMEM = 1024 * SMX_STRIDE * 4;  // 135168
  cudaFuncSetAttribute(softmax_pack_kernel,
                       cudaFuncAttributeMaxDynamicSharedMemorySize, SMX_SMEM);

  dim3 cg(16, 8, 16);
  conv_split_kernel<<<cg, 256>>>(enc, out, 0);
  conv_split_kernel<<<cg, 256>>>(dec, out, 1);  // also writes out[:, :1024]

  dim3 gg(16, 8, 16);
  hmma_gemm_kernel<0><<<gg, 256, 98304>>>(out);

  dim3 gs(32, 16);
  softmax_pack_kernel<<<gs, dim3(32, 16), SMX_SMEM>>>();

  hmma_gemm_kernel<1><<<gg, 256, 98304>>>(out);
}

// round 8
// speedup vs baseline: 2.7383x; 1.0339x over previous
#include <cuda_runtime.h>
#include <cuda_bf16.h>
#include <cstdint>

// B=16, Te=1024, Td=1024, D=1024
//   S[b,e,t]   = enc[b,e,:] . dec[b,t,:]          (GEMM1)
//   A          = softmax_e(S)
//   ctx[b,t,d] = sum_e A[e,t] enc[e,d]            (GEMM2: A from attT panels,
//                                                  B from encP via ldmatrix.trans)
//   out        = concat(dec, ctx)                 [B, Td, 2048]
//
// Tensor cores via mma.sync bf16 hi/lo split: a*b ~= ah*bh + ah*bl + al*bh

#define PANEL_U4 1024  // one 128x64-bf16 SW128 panel = 16KB = 1024 uint4
#define NPANEL 2048    // 16 b * 8 rowblk * 16 kblk

__device__ float g_S[(size_t)16 * 1024 * 1024];  // fp32 scores
__device__ uint4 g_encPh[NPANEL * PANEL_U4], g_encPl[NPANEL * PANEL_U4];  // enc [e,d]
__device__ uint4 g_decPh[NPANEL * PANEL_U4], g_decPl[NPANEL * PANEL_U4];  // dec [t,d]
__device__ uint4 g_attTh[NPANEL * PANEL_U4], g_attTl[NPANEL * PANEL_U4];  // attn^T [t,e]

// ---------------------------------------------------------------------------
static __device__ __forceinline__ uint32_t smem_u32(const void* p) {
  uint32_t a;
  asm("{ .reg .u64 t; cvta.to.shared.u64 t, %1; cvt.u32.u64 %0, t; }"
      : "=r"(a) : "l"(p));
  return a;
}
static __device__ __forceinline__ uint32_t swz(uint32_t x) {
  return x ^ ((x >> 3) & 0x70);
}
static __device__ __forceinline__ void cp_async16(uint32_t dst,
                                                  const void* src) {
  asm volatile("cp.async.cg.shared.global [%0], [%1], 16;"
               :: "r"(dst), "l"(src) : "memory");
}
static __device__ __forceinline__ void ldsm4(uint32_t* r, uint32_t addr) {
  asm volatile(
      "ldmatrix.sync.aligned.m8n8.x4.shared.b16 {%0,%1,%2,%3}, [%4];"
      : "=r"(r[0]), "=r"(r[1]), "=r"(r[2]), "=r"(r[3])
      : "r"(addr));
}
static __device__ __forceinline__ void ldsm4t(uint32_t* r, uint32_t addr) {
  asm volatile(
      "ldmatrix.sync.aligned.m8n8.x4.trans.shared.b16 {%0,%1,%2,%3}, [%4];"
      : "=r"(r[0]), "=r"(r[1]), "=r"(r[2]), "=r"(r[3])
      : "r"(addr));
}
static __device__ __forceinline__ void mma16816(float* c, const uint32_t* a,
                                                const uint32_t* b) {
  asm volatile(
      "mma.sync.aligned.m16n8k16.row.col.f32.bf16.bf16.f32 "
      "{%0,%1,%2,%3}, {%4,%5,%6,%7}, {%8,%9}, {%0,%1,%2,%3};"
      : "+f"(c[0]), "+f"(c[1]), "+f"(c[2]), "+f"(c[3])
      : "r"(a[0]), "r"(a[1]), "r"(a[2]), "r"(a[3]), "r"(b[0]), "r"(b[1]));
}
static __device__ __forceinline__ uint32_t cvt_bf16x2(float hi, float lo) {
  uint32_t r;
  asm("cvt.rn.bf16x2.f32 %0, %1, %2;" : "=r"(r) : "f"(hi), "f"(lo));
  return r;
}
// hi/lo split, 2 elems/cvt; bf16->f32 via exact bit-shift
static __device__ __forceinline__ void split8(const float* f, uint4& H,
                                              uint4& L) {
  uint32_t h[4], l[4];
#pragma unroll
  for (int j = 0; j < 4; ++j) {
    const float f0 = f[2 * j], f1 = f[2 * j + 1];
    const uint32_t hu = cvt_bf16x2(f1, f0);  // lo half = f0
    const float fh0 = __uint_as_float(hu << 16);
    const float fh1 = __uint_as_float(hu & 0xFFFF0000u);
    h[j] = hu;
    l[j] = cvt_bf16x2(f1 - fh1, f0 - fh0);
  }
  H = make_uint4(h[0], h[1], h[2], h[3]);
  L = make_uint4(l[0], l[1], l[2], l[3]);
}

// ---------------------------------------------------------------------------
// Pack: fp32 [rows,1024] -> SW128 bf16 hi/lo panels. grid (kb16, rb8, b16).
// which: 0 = enc->encP; 1 = dec->decP and ALSO copy dec into out[..., 0:1024]
// ---------------------------------------------------------------------------
__global__ __launch_bounds__(256) void conv_split_kernel(
    const float* __restrict__ src, float* __restrict__ out, int which) {
  uint4* dh = which ? g_decPh : g_encPh;
  uint4* dl = which ? g_decPl : g_encPl;
  const int kb = blockIdx.x, rb = blockIdx.y, b = blockIdx.z;
  const size_t panel = ((size_t)(b * 8 + rb) * 16 + kb) * PANEL_U4;
  const float* sp = src + ((size_t)b * 1024 + rb * 128) * 1024 + kb * 64;
#pragma unroll
  for (int it = 0; it < 4; ++it) {
    const int chunk = it * 256 + threadIdx.x;
    const int r = chunk >> 3, cc = chunk & 7;
    const float4* s4 =
        reinterpret_cast<const float4*>(sp + (size_t)r * 1024 + cc * 8);
    float4 x0 = s4[0], x1 = s4[1];
    float f[8] = {x0.x, x0.y, x0.z, x0.w, x1.x, x1.y, x1.z, x1.w};
    uint4 H, L;
    split8(f, H, L);
    const uint32_t off = swz((uint32_t)(r * 128 + cc * 16)) >> 4;
    dh[panel + off] = H;
    dl[panel + off] = L;
    if (which) {
      float4* o4 = reinterpret_cast<float4*>(
          out + ((size_t)(b * 1024 + rb * 128 + r)) * 2048 + kb * 64 + cc * 8);
      o4[0] = x0;
      o4[1] = x1;
    }
  }
}

// ---------------------------------------------------------------------------
// Softmax over e + transpose + bf16 hi/lo pack of attn^T [t,e].
// One CTA per (b, 16 t-cols): stage full 1024x16 score tile in ~70KB smem
// (3 CTAs/SM). pass1 max, pass2 exp once + sum, pass3 scale+transpose+pack.
// grid (tchunk=64, b=16), block (16, 32) = 512 threads.
// ---------------------------------------------------------------------------
#define SMX_STRIDE 17
__global__ __launch_bounds__(512) void softmax_pack_kernel() {
  extern __shared__ __align__(16) float tile[];  // [1024][17]
  __shared__ float sred[32][16], Mv[16], Iv[16];

  const int b = blockIdx.y;
  const int t0 = blockIdx.x * 16;
  const int tx = threadIdx.x;  // t-col 0..15
  const int ty = threadIdx.y;  // e-lane 0..31
  const int ltid = ty * 16 + tx;
  const float* Sb = g_S + (size_t)b * 1024 * 1024 + t0;

  // pass 1: load into smem + per-thread max (no exp)
  float m = -3.402823466e38f;
#pragma unroll 8
  for (int e = ty; e < 1024; e += 32) {
    const float v = Sb[(size_t)e * 1024 + tx];
    tile[e * SMX_STRIDE + tx] = v;
    m = fmaxf(m, v);
  }
  sred[ty][tx] = m;
  __syncthreads();
  if (ty == 0) {
    float M = sred[0][tx];
#pragma unroll
    for (int i = 1; i < 32; ++i) M = fmaxf(M, sred[i][tx]);
    Mv[tx] = M;
  }
  __syncthreads();

  // pass 2: exp once into smem + per-thread sum
  const float M = Mv[tx];
  float s = 0.f;
#pragma unroll 8
  for (int e = ty; e < 1024; e += 32) {
    const float p = __expf(tile[e * SMX_STRIDE + tx] - M);
    tile[e * SMX_STRIDE + tx] = p;
    s += p;
  }
  sred[ty][tx] = s;
  __syncthreads();
  if (ty == 0) {
    float S = sred[0][tx];
#pragma unroll
    for (int i = 1; i < 32; ++i) S += sred[i][tx];
    Iv[tx] = 1.f / S;
  }
  __syncthreads();

  // pass 3: scale + transpose + hi/lo pack (read-only smem, no syncs)
  const int tb = t0 >> 7;        // which 128-row panel block
  const int tl0 = t0 & 127;      // row offset within panel
  const int ebh = ltid >> 7;     // 0..3: eb residue
  const int chunk = ltid & 127;  // 128 tasks: 16 t-rows x 8 ec
  const int tl = chunk >> 3, ec = chunk & 7;
  const float inv = Iv[tl];
#pragma unroll
  for (int ebp = 0; ebp < 4; ++ebp) {
    const int eb = ebp * 4 + ebh;
    float f[8];
#pragma unroll
    for (int j = 0; j < 8; ++j)
      f[j] = tile[(eb * 64 + ec * 8 + j) * SMX_STRIDE + tl] * inv;
    uint4 H, L;
    split8(f, H, L);
    const size_t panel = ((size_t)(b * 8 + tb) * 16 + eb) * PANEL_U4;
    const uint32_t off = swz((uint32_t)((tl0 + tl) * 128 + ec * 16)) >> 4;
    g_attTh[panel + off] = H;
    g_attTl[panel + off] = L;
  }
}

// ---------------------------------------------------------------------------
// HMMA GEMM: C tile 128(M) x 64(N) fp32, K=1024, bf16 hi/lo split (3 MMAs).
// grid (nbk=16, mbk=8, b=16), 256 threads (8 warps: 4 m x 2 n, warp 32x32),
// BK=64, 2-stage cp.async pipeline (single barrier per chunk),
// 48KB/stage => 96KB => 2 CTAs/SM.
// WHICH=0: GEMM1 encP x decP -> g_S        (B non-trans, [n,k]-major panels)
// WHICH=1: GEMM2 attT x encP -> out ctx    (B via ldmatrix.trans, [k,n]-major)
// ---------------------------------------------------------------------------
template <int WHICH>
__global__ __launch_bounds__(256, 2) void hmma_gemm_kernel(
    float* __restrict__ o) {
  extern __shared__ __align__(16) char dsm[];
  const uint4* Ah = WHICH ? g_attTh : g_encPh;
  const uint4* Al = WHICH ? g_attTl : g_encPl;
  const uint4* Bh = WHICH ? g_encPh : g_decPh;
  const uint4* Bl = WHICH ? g_encPl : g_decPl;
  float* C;
  int ldc, coff;
  size_t bstride;
  if (WHICH == 0) {
    C = g_S; ldc = 1024; coff = 0; bstride = (size_t)1024 * 1024;
  } else {
    C = o; ldc = 2048; coff = 1024; bstride = (size_t)1024 * 2048;
  }

  const int tid = threadIdx.x;
  const int wid = tid >> 5, lane = tid & 31;
  const int wm = wid & 3, wn = wid >> 2;  // warp tile: rows wm*32, cols wn*32
  const int b = blockIdx.z, mbk = blockIdx.y, nbk = blockIdx.x;
  const size_t apan = ((size_t)(b * 8 + mbk)) * 16;
  const uint32_t smem_base = smem_u32(dsm);

  // stage layout: Ah 0..16K, Al 16K..32K, Bh 32K..40K, Bl 40K..48K
  auto issue_chunk = [&](int c) {
    const uint32_t base = smem_base + (uint32_t)(c & 1) * 49152u;
    const uint4* a0 = Ah + (apan + c) * PANEL_U4;
    const uint4* a1 = Al + (apan + c) * PANEL_U4;
    size_t bpan;
    int brow0;
    if (WHICH == 0) {  // B = dec [t,d]: panel rowblk = t (nbk), kblk = d (c)
      bpan = ((size_t)(b * 8 + (nbk >> 1)) * 16 + c) * PANEL_U4;
      brow0 = (nbk & 1) * 64;
    } else {  // B = enc [e,d]: panel rowblk = e (c), kblk = d (nbk)
      bpan = ((size_t)(b * 8 + (c >> 1)) * 16 + nbk) * PANEL_U4;
      brow0 = (c & 1) * 64;
    }
    const uint4* b0 = Bh + bpan;
    const uint4* b1 = Bl + bpan;
#pragma unroll
    for (int j = 0; j < 4; ++j) {  // A: 2048 uint4
      const int i = tid + j * 256;
      cp_async16(base + (uint32_t)i * 16u, a0 + i);
      cp_async16(base + 16384u + (uint32_t)i * 16u, a1 + i);
    }
#pragma unroll
    for (int j = 0; j < 2; ++j) {  // B: 64 rows of the 128-row panel
      const int lu = tid + j * 256;  // 0..511
      const int prow = brow0 + (lu >> 3), uin = lu & 7;
      cp_async16(base + 32768u + (uint32_t)lu * 16u, b0 + prow * 8 + uin);
      cp_async16(base + 40960u + (uint32_t)lu * 16u, b1 + prow * 8 + uin);
    }
    asm volatile("cp.async.commit_group;" ::: "memory");
  };

  float acc[2][4][4];
#pragma unroll
  for (int mt = 0; mt < 2; ++mt)
#pragma unroll
    for (int nt = 0; nt < 4; ++nt)
#pragma unroll
      for (int j = 0; j < 4; ++j) acc[mt][nt][j] = 0.f;

  issue_chunk(0);

  const uint32_t a_row = (uint32_t)(wm * 32 + (lane & 15));
  const uint32_t a_koff = (lane & 16) ? 16u : 0u;
  const uint32_t b_row =
      (uint32_t)(wn * 32 + (lane & 7) + ((lane & 16) ? 8 : 0));
  const uint32_t b_koff = (lane & 8) ? 16u : 0u;
  const uint32_t bt_krow = (uint32_t)(lane & 15);
  const uint32_t bt_coff = (uint32_t)(wn * 32 + ((lane & 16) ? 8 : 0)) * 2u;

  for (int c = 0; c < 16; ++c) {
    // wait for group c (the only outstanding group), then ONE barrier;
    // prefetch of c+1 is safe: its buffer was consumed in iteration c-1,
    // and the barrier proves all warps finished that compute.
    asm volatile("cp.async.wait_group 0;" ::: "memory");
    __syncthreads();
    if (c + 1 < 16) issue_chunk(c + 1);

    const uint32_t sb = smem_base + (uint32_t)(c & 1) * 49152u;
    const uint32_t Ah_b = sb, Al_b = sb + 16384u;
    const uint32_t Bh_b = sb + 32768u, Bl_b = sb + 40960u;

#pragma unroll
    for (int kk = 0; kk < 4; ++kk) {
      uint32_t ah[2][4], al[2][4];
#pragma unroll
      for (int mt = 0; mt < 2; ++mt) {
        const uint32_t byte = swz((a_row + (uint32_t)mt * 16u) * 128u +
                                  (uint32_t)kk * 32u + a_koff);
        ldsm4(ah[mt], Ah_b + byte);
        ldsm4(al[mt], Al_b + byte);
      }
      uint32_t bh[2][4], bl[2][4];
#pragma unroll
      for (int np = 0; np < 2; ++np) {
        if (WHICH == 0) {
          const uint32_t byte = swz((b_row + (uint32_t)np * 16u) * 128u +
                                    (uint32_t)kk * 32u + b_koff);
          ldsm4(bh[np], Bh_b + byte);
          ldsm4(bl[np], Bl_b + byte);
        } else {
          const uint32_t byte =
              swz(((uint32_t)kk * 16u + bt_krow) * 128u + bt_coff +
                  (uint32_t)np * 32u);
          ldsm4t(bh[np], Bh_b + byte);
          ldsm4t(bl[np], Bl_b + byte);
        }
      }
#pragma unroll
      for (int mt = 0; mt < 2; ++mt)
#pragma unroll
        for (int nt = 0; nt < 4; ++nt) {
          const uint32_t* B0 = &bh[nt >> 1][(nt & 1) * 2];
          const uint32_t* B1 = &bl[nt >> 1][(nt & 1) * 2];
          mma16816(acc[mt][nt], ah[mt], B0);
          mma16816(acc[mt][nt], ah[mt], B1);
          mma16816(acc[mt][nt], al[mt], B0);
        }
    }
  }

  float* Cb = C + (size_t)b * bstride + (size_t)(mbk * 128) * ldc + coff +
              nbk * 64;
  const int g = lane >> 2, tig = lane & 3;
#pragma unroll
  for (int mt = 0; mt < 2; ++mt)
#pragma unroll
    for (int nt = 0; nt < 4; ++nt) {
      const int row = wm * 32 + mt * 16 + g;
      const int col = wn * 32 + nt * 8 + tig * 2;
      *reinterpret_cast<float2*>(Cb + (size_t)row * ldc + col) =
          make_float2(acc[mt][nt][0], acc[mt][nt][1]);
      *reinterpret_cast<float2*>(Cb + (size_t)(row + 8) * ldc + col) =
          make_float2(acc[mt][nt][2], acc[mt][nt][3]);
    }
}

// ---------------------------------------------------------------------------
extern "C" void kernel_launch(void* const* d_in, const int* in_sizes, int n_in,
                              void* d_out, int out_size) {
  const float* enc = (const float*)d_in[0];
  const float* dec = (const float*)d_in[1];
  float* out = (float*)d_out;

  cudaFuncSetAttribute(hmma_gemm_kernel<0>,
                       cudaFuncAttributeMaxDynamicSharedMemorySize, 98304);
  cudaFuncSetAttribute(hmma_gemm_kernel<1>,
                       cudaFuncAttributeMaxDynamicSharedMemorySize, 98304);
  const int SMX_SMEM = 1024 * SMX_STRIDE * 4;  // 69632
  cudaFuncSetAttribute(softmax_pack_kernel,
                       cudaFuncAttributeMaxDynamicSharedMemorySize, SMX_SMEM);

  dim3 cg(16, 8, 16);
  conv_split_kernel<<<cg, 256>>>(enc, out, 0);
  conv_split_kernel<<<cg, 256>>>(dec, out, 1);  // also writes out[:, :1024]

  dim3 gg(16, 8, 16);
  hmma_gemm_kernel<0><<<gg, 256, 98304>>>(out);

  dim3 gs(64, 16);
  softmax_pack_kernel<<<gs, dim3(16, 32), SMX_SMEM>>>();

  hmma_gemm_kernel<1><<<gg, 256, 98304>>>(out);
}

// round 9
// speedup vs baseline: 2.8441x; 1.0387x over previous
#include <cuda_runtime.h>
#include <cuda_bf16.h>
#include <cstdint>

// B=16, Te=1024, Td=1024, D=1024
//   S'[b,t,e]  = dec[b,t,:] . enc[b,e,:]          (GEMM1, transposed scores)
//   A'[t,e]    = row-softmax_e(S')                (contiguous softmax)
//   ctx[b,t,d] = sum_e A'[t,e] enc[e,d]           (GEMM2: A from attT panels,
//                                                  B from encP via ldmatrix.trans)
//   out        = concat(dec, ctx)                 [B, Td, 2048]
//
// Tensor cores via mma.sync bf16 hi/lo split: a*b ~= ah*bh + ah*bl + al*bh

#define PANEL_U4 1024  // one 128x64-bf16 SW128 panel = 16KB = 1024 uint4
#define NPANEL 2048    // 16 b * 8 rowblk * 16 kblk

__device__ float g_S[(size_t)16 * 1024 * 1024];  // fp32 scores S'[t,e]
__device__ uint4 g_encPh[NPANEL * PANEL_U4], g_encPl[NPANEL * PANEL_U4];  // enc [e,d]
__device__ uint4 g_decPh[NPANEL * PANEL_U4], g_decPl[NPANEL * PANEL_U4];  // dec [t,d]
__device__ uint4 g_attTh[NPANEL * PANEL_U4], g_attTl[NPANEL * PANEL_U4];  // attn' [t,e]

// ---------------------------------------------------------------------------
static __device__ __forceinline__ uint32_t smem_u32(const void* p) {
  uint32_t a;
  asm("{ .reg .u64 t; cvta.to.shared.u64 t, %1; cvt.u32.u64 %0, t; }"
      : "=r"(a) : "l"(p));
  return a;
}
static __device__ __forceinline__ uint32_t swz(uint32_t x) {
  return x ^ ((x >> 3) & 0x70);
}
static __device__ __forceinline__ void cp_async16(uint32_t dst,
                                                  const void* src) {
  asm volatile("cp.async.cg.shared.global [%0], [%1], 16;"
               :: "r"(dst), "l"(src) : "memory");
}
static __device__ __forceinline__ void ldsm4(uint32_t* r, uint32_t addr) {
  asm volatile(
      "ldmatrix.sync.aligned.m8n8.x4.shared.b16 {%0,%1,%2,%3}, [%4];"
      : "=r"(r[0]), "=r"(r[1]), "=r"(r[2]), "=r"(r[3])
      : "r"(addr));
}
static __device__ __forceinline__ void ldsm4t(uint32_t* r, uint32_t addr) {
  asm volatile(
      "ldmatrix.sync.aligned.m8n8.x4.trans.shared.b16 {%0,%1,%2,%3}, [%4];"
      : "=r"(r[0]), "=r"(r[1]), "=r"(r[2]), "=r"(r[3])
      : "r"(addr));
}
static __device__ __forceinline__ void mma16816(float* c, const uint32_t* a,
                                                const uint32_t* b) {
  asm volatile(
      "mma.sync.aligned.m16n8k16.row.col.f32.bf16.bf16.f32 "
      "{%0,%1,%2,%3}, {%4,%5,%6,%7}, {%8,%9}, {%0,%1,%2,%3};"
      : "+f"(c[0]), "+f"(c[1]), "+f"(c[2]), "+f"(c[3])
      : "r"(a[0]), "r"(a[1]), "r"(a[2]), "r"(a[3]), "r"(b[0]), "r"(b[1]));
}
static __device__ __forceinline__ uint32_t cvt_bf16x2(float hi, float lo) {
  uint32_t r;
  asm("cvt.rn.bf16x2.f32 %0, %1, %2;" : "=r"(r) : "f"(hi), "f"(lo));
  return r;
}
// hi/lo split, 2 elems/cvt; bf16->f32 via exact bit-shift
static __device__ __forceinline__ void split8(const float* f, uint4& H,
                                              uint4& L) {
  uint32_t h[4], l[4];
#pragma unroll
  for (int j = 0; j < 4; ++j) {
    const float f0 = f[2 * j], f1 = f[2 * j + 1];
    const uint32_t hu = cvt_bf16x2(f1, f0);  // lo half = f0
    const float fh0 = __uint_as_float(hu << 16);
    const float fh1 = __uint_as_float(hu & 0xFFFF0000u);
    h[j] = hu;
    l[j] = cvt_bf16x2(f1 - fh1, f0 - fh0);
  }
  H = make_uint4(h[0], h[1], h[2], h[3]);
  L = make_uint4(l[0], l[1], l[2], l[3]);
}

// ---------------------------------------------------------------------------
// Pack: fp32 [rows,1024] -> SW128 bf16 hi/lo panels. grid (kb16, rb8, b16).
// which: 0 = enc->encP; 1 = dec->decP and ALSO copy dec into out[..., 0:1024]
// ---------------------------------------------------------------------------
__global__ __launch_bounds__(256) void conv_split_kernel(
    const float* __restrict__ src, float* __restrict__ out, int which) {
  uint4* dh = which ? g_decPh : g_encPh;
  uint4* dl = which ? g_decPl : g_encPl;
  const int kb = blockIdx.x, rb = blockIdx.y, b = blockIdx.z;
  const size_t panel = ((size_t)(b * 8 + rb) * 16 + kb) * PANEL_U4;
  const float* sp = src + ((size_t)b * 1024 + rb * 128) * 1024 + kb * 64;
#pragma unroll
  for (int it = 0; it < 4; ++it) {
    const int chunk = it * 256 + threadIdx.x;
    const int r = chunk >> 3, cc = chunk & 7;
    const float4* s4 =
        reinterpret_cast<const float4*>(sp + (size_t)r * 1024 + cc * 8);
    float4 x0 = s4[0], x1 = s4[1];
    float f[8] = {x0.x, x0.y, x0.z, x0.w, x1.x, x1.y, x1.z, x1.w};
    uint4 H, L;
    split8(f, H, L);
    const uint32_t off = swz((uint32_t)(r * 128 + cc * 16)) >> 4;
    dh[panel + off] = H;
    dl[panel + off] = L;
    if (which) {
      float4* o4 = reinterpret_cast<float4*>(
          out + ((size_t)(b * 1024 + rb * 128 + r)) * 2048 + kb * 64 + cc * 8);
      o4[0] = x0;
      o4[1] = x1;
    }
  }
}

// ---------------------------------------------------------------------------
// Row softmax of S'[t,e] + bf16 hi/lo pack to attn' panels [t-rowblk][e-kblk].
// One warp per t-row: coalesced loads, warp-shuffle max/sum, exp once,
// direct panel pack (no transpose, no smem tile).
// grid (128, b=16), block 256 (8 warps = 8 rows).
// ---------------------------------------------------------------------------
__global__ __launch_bounds__(256) void softmax_pack_kernel() {
  const int b = blockIdx.y;
  const int t = blockIdx.x * 8 + (threadIdx.x >> 5);
  const int lane = threadIdx.x & 31;
  const float* Sr = g_S + ((size_t)b * 1024 + t) * 1024;

  // lane holds e = i*256 + lane*8 .. +7  (i = 0..3): 8 contiguous per group
  float f[4][8];
  float m = -3.402823466e38f;
#pragma unroll
  for (int i = 0; i < 4; ++i) {
    const float4* p = reinterpret_cast<const float4*>(Sr + i * 256 + lane * 8);
    const float4 x0 = p[0], x1 = p[1];
    f[i][0] = x0.x; f[i][1] = x0.y; f[i][2] = x0.z; f[i][3] = x0.w;
    f[i][4] = x1.x; f[i][5] = x1.y; f[i][6] = x1.z; f[i][7] = x1.w;
#pragma unroll
    for (int j = 0; j < 8; ++j) m = fmaxf(m, f[i][j]);
  }
#pragma unroll
  for (int o = 16; o; o >>= 1)
    m = fmaxf(m, __shfl_xor_sync(0xffffffffu, m, o));

  float s = 0.f;
#pragma unroll
  for (int i = 0; i < 4; ++i)
#pragma unroll
    for (int j = 0; j < 8; ++j) {
      f[i][j] = __expf(f[i][j] - m);
      s += f[i][j];
    }
#pragma unroll
  for (int o = 16; o; o >>= 1) s += __shfl_xor_sync(0xffffffffu, s, o);
  const float inv = 1.f / s;

  const int tb = t >> 7, tl = t & 127;
  const uint32_t off = swz((uint32_t)(tl * 128 + (lane & 7) * 16)) >> 4;
#pragma unroll
  for (int i = 0; i < 4; ++i) {
#pragma unroll
    for (int j = 0; j < 8; ++j) f[i][j] *= inv;
    uint4 H, L;
    split8(f[i], H, L);
    const int eb = i * 4 + (lane >> 3);
    const size_t panel = ((size_t)(b * 8 + tb) * 16 + eb) * PANEL_U4;
    g_attTh[panel + off] = H;
    g_attTl[panel + off] = L;
  }
}

// ---------------------------------------------------------------------------
// HMMA GEMM: C tile 128(M) x 64(N) fp32, K=1024, bf16 hi/lo split (3 MMAs).
// grid (nbk=16, mbk=8, b=16), 256 threads (8 warps: 4 m x 2 n, warp 32x32),
// BK=64, 2-stage cp.async pipeline (single barrier per chunk),
// 48KB/stage => 96KB => 2 CTAs/SM.
// WHICH=0: GEMM1 decP x encP -> g_S (S'[t,e])   (B non-trans, [n,k] panels)
// WHICH=1: GEMM2 attT x encP -> out ctx         (B via ldmatrix.trans)
// ---------------------------------------------------------------------------
template <int WHICH>
__global__ __launch_bounds__(256, 2) void hmma_gemm_kernel(
    float* __restrict__ o) {
  extern __shared__ __align__(16) char dsm[];
  const uint4* Ah = WHICH ? g_attTh : g_decPh;
  const uint4* Al = WHICH ? g_attTl : g_decPl;
  const uint4* Bh = g_encPh;
  const uint4* Bl = g_encPl;
  float* C;
  int ldc, coff;
  size_t bstride;
  if (WHICH == 0) {
    C = g_S; ldc = 1024; coff = 0; bstride = (size_t)1024 * 1024;
  } else {
    C = o; ldc = 2048; coff = 1024; bstride = (size_t)1024 * 2048;
  }

  const int tid = threadIdx.x;
  const int wid = tid >> 5, lane = tid & 31;
  const int wm = wid & 3, wn = wid >> 2;  // warp tile: rows wm*32, cols wn*32
  const int b = blockIdx.z, mbk = blockIdx.y, nbk = blockIdx.x;
  const size_t apan = ((size_t)(b * 8 + mbk)) * 16;
  const uint32_t smem_base = smem_u32(dsm);

  // stage layout: Ah 0..16K, Al 16K..32K, Bh 32K..40K, Bl 40K..48K
  auto issue_chunk = [&](int c) {
    const uint32_t base = smem_base + (uint32_t)(c & 1) * 49152u;
    const uint4* a0 = Ah + (apan + c) * PANEL_U4;
    const uint4* a1 = Al + (apan + c) * PANEL_U4;
    size_t bpan;
    int brow0;
    if (WHICH == 0) {  // B = enc [e,d]: panel rowblk = e (nbk), kblk = d (c)
      bpan = ((size_t)(b * 8 + (nbk >> 1)) * 16 + c) * PANEL_U4;
      brow0 = (nbk & 1) * 64;
    } else {  // B = enc [e,d]: panel rowblk = e (c), kblk = d (nbk)
      bpan = ((size_t)(b * 8 + (c >> 1)) * 16 + nbk) * PANEL_U4;
      brow0 = (c & 1) * 64;
    }
    const uint4* b0 = Bh + bpan;
    const uint4* b1 = Bl + bpan;
#pragma unroll
    for (int j = 0; j < 4; ++j) {  // A: 2048 uint4
      const int i = tid + j * 256;
      cp_async16(base + (uint32_t)i * 16u, a0 + i);
      cp_async16(base + 16384u + (uint32_t)i * 16u, a1 + i);
    }
#pragma unroll
    for (int j = 0; j < 2; ++j) {  // B: 64 rows of the 128-row panel
      const int lu = tid + j * 256;  // 0..511
      const int prow = brow0 + (lu >> 3), uin = lu & 7;
      cp_async16(base + 32768u + (uint32_t)lu * 16u, b0 + prow * 8 + uin);
      cp_async16(base + 40960u + (uint32_t)lu * 16u, b1 + prow * 8 + uin);
    }
    asm volatile("cp.async.commit_group;" ::: "memory");
  };

  float acc[2][4][4];
#pragma unroll
  for (int mt = 0; mt < 2; ++mt)
#pragma unroll
    for (int nt = 0; nt < 4; ++nt)
#pragma unroll
      for (int j = 0; j < 4; ++j) acc[mt][nt][j] = 0.f;

  issue_chunk(0);

  const uint32_t a_row = (uint32_t)(wm * 32 + (lane & 15));
  const uint32_t a_koff = (lane & 16) ? 16u : 0u;
  const uint32_t b_row =
      (uint32_t)(wn * 32 + (lane & 7) + ((lane & 16) ? 8 : 0));
  const uint32_t b_koff = (lane & 8) ? 16u : 0u;
  const uint32_t bt_krow = (uint32_t)(lane & 15);
  const uint32_t bt_coff = (uint32_t)(wn * 32 + ((lane & 16) ? 8 : 0)) * 2u;

  for (int c = 0; c < 16; ++c) {
    asm volatile("cp.async.wait_group 0;" ::: "memory");
    __syncthreads();
    if (c + 1 < 16) issue_chunk(c + 1);

    const uint32_t sb = smem_base + (uint32_t)(c & 1) * 49152u;
    const uint32_t Ah_b = sb, Al_b = sb + 16384u;
    const uint32_t Bh_b = sb + 32768u, Bl_b = sb + 40960u;

#pragma unroll
    for (int kk = 0; kk < 4; ++kk) {
      uint32_t ah[2][4], al[2][4];
#pragma unroll
      for (int mt = 0; mt < 2; ++mt) {
        const uint32_t byte = swz((a_row + (uint32_t)mt * 16u) * 128u +
                                  (uint32_t)kk * 32u + a_koff);
        ldsm4(ah[mt], Ah_b + byte);
        ldsm4(al[mt], Al_b + byte);
      }
      uint32_t bh[2][4], bl[2][4];
#pragma unroll
      for (int np = 0; np < 2; ++np) {
        if (WHICH == 0) {
          const uint32_t byte = swz((b_row + (uint32_t)np * 16u) * 128u +
                                    (uint32_t)kk * 32u + b_koff);
          ldsm4(bh[np], Bh_b + byte);
          ldsm4(bl[np], Bl_b + byte);
        } else {
          const uint32_t byte =
              swz(((uint32_t)kk * 16u + bt_krow) * 128u + bt_coff +
                  (uint32_t)np * 32u);
          ldsm4t(bh[np], Bh_b + byte);
          ldsm4t(bl[np], Bl_b + byte);
        }
      }
#pragma unroll
      for (int mt = 0; mt < 2; ++mt)
#pragma unroll
        for (int nt = 0; nt < 4; ++nt) {
          const uint32_t* B0 = &bh[nt >> 1][(nt & 1) * 2];
          const uint32_t* B1 = &bl[nt >> 1][(nt & 1) * 2];
          mma16816(acc[mt][nt], ah[mt], B0);
          mma16816(acc[mt][nt], ah[mt], B1);
          mma16816(acc[mt][nt], al[mt], B0);
        }
    }
  }

  float* Cb = C + (size_t)b * bstride + (size_t)(mbk * 128) * ldc + coff +
              nbk * 64;
  const int g = lane >> 2, tig = lane & 3;
#pragma unroll
  for (int mt = 0; mt < 2; ++mt)
#pragma unroll
    for (int nt = 0; nt < 4; ++nt) {
      const int row = wm * 32 + mt * 16 + g;
      const int col = wn * 32 + nt * 8 + tig * 2;
      *reinterpret_cast<float2*>(Cb + (size_t)row * ldc + col) =
          make_float2(acc[mt][nt][0], acc[mt][nt][1]);
      *reinterpret_cast<float2*>(Cb + (size_t)(row + 8) * ldc + col) =
          make_float2(acc[mt][nt][2], acc[mt][nt][3]);
    }
}

// ---------------------------------------------------------------------------
extern "C" void kernel_launch(void* const* d_in, const int* in_sizes, int n_in,
                              void* d_out, int out_size) {
  const float* enc = (const float*)d_in[0];
  const float* dec = (const float*)d_in[1];
  float* out = (float*)d_out;

  cudaFuncSetAttribute(hmma_gemm_kernel<0>,
                       cudaFuncAttributeMaxDynamicSharedMemorySize, 98304);
  cudaFuncSetAttribute(hmma_gemm_kernel<1>,
                       cudaFuncAttributeMaxDynamicSharedMemorySize, 98304);

  dim3 cg(16, 8, 16);
  conv_split_kernel<<<cg, 256>>>(enc, out, 0);
  conv_split_kernel<<<cg, 256>>>(dec, out, 1);  // also writes out[:, :1024]

  dim3 gg(16, 8, 16);
  hmma_gemm_kernel<0><<<gg, 256, 98304>>>(out);

  softmax_pack_kernel<<<dim3(128, 16), 256>>>();

  hmma_gemm_kernel<1><<<gg, 256, 98304>>>(out);
}

// round 10
// speedup vs baseline: 2.9495x; 1.0370x over previous
#include <cuda_runtime.h>
#include <cuda_bf16.h>
#include <cstdint>

// B=16, Te=1024, Td=1024, D=1024
//   S'[b,t,e]  = dec[b,t,:] . enc[b,e,:]          (GEMM1, transposed scores)
//   A'[t,e]    = row-softmax_e(S')                (contiguous softmax)
//   ctx[b,t,d] = sum_e A'[t,e] enc[e,d]           (GEMM2: A from attT panels,
//                                                  B from encP via ldmatrix.trans)
//   out        = concat(dec, ctx)                 [B, Td, 2048]
//
// Tensor cores via mma.sync bf16 hi/lo split: a*b ~= ah*bh + ah*bl + al*bh

#define PANEL_U4 1024  // one 128x64-bf16 SW128 panel = 16KB = 1024 uint4
#define NPANEL 2048    // 16 b * 8 rowblk * 16 kblk

__device__ float g_S[(size_t)16 * 1024 * 1024];  // fp32 scores S'[t,e]
__device__ uint4 g_encPh[NPANEL * PANEL_U4], g_encPl[NPANEL * PANEL_U4];  // enc [e,d]
__device__ uint4 g_decPh[NPANEL * PANEL_U4], g_decPl[NPANEL * PANEL_U4];  // dec [t,d]
__device__ uint4 g_attTh[NPANEL * PANEL_U4], g_attTl[NPANEL * PANEL_U4];  // attn' [t,e]

// ---------------------------------------------------------------------------
static __device__ __forceinline__ uint32_t smem_u32(const void* p) {
  uint32_t a;
  asm("{ .reg .u64 t; cvta.to.shared.u64 t, %1; cvt.u32.u64 %0, t; }"
      : "=r"(a) : "l"(p));
  return a;
}
static __device__ __forceinline__ uint32_t swz(uint32_t x) {
  return x ^ ((x >> 3) & 0x70);
}
static __device__ __forceinline__ void cp_async16(uint32_t dst,
                                                  const void* src) {
  asm volatile("cp.async.cg.shared.global [%0], [%1], 16;"
               :: "r"(dst), "l"(src) : "memory");
}
static __device__ __forceinline__ void ldsm4(uint32_t* r, uint32_t addr) {
  asm volatile(
      "ldmatrix.sync.aligned.m8n8.x4.shared.b16 {%0,%1,%2,%3}, [%4];"
      : "=r"(r[0]), "=r"(r[1]), "=r"(r[2]), "=r"(r[3])
      : "r"(addr));
}
static __device__ __forceinline__ void ldsm4t(uint32_t* r, uint32_t addr) {
  asm volatile(
      "ldmatrix.sync.aligned.m8n8.x4.trans.shared.b16 {%0,%1,%2,%3}, [%4];"
      : "=r"(r[0]), "=r"(r[1]), "=r"(r[2]), "=r"(r[3])
      : "r"(addr));
}
static __device__ __forceinline__ void mma16816(float* c, const uint32_t* a,
                                                const uint32_t* b) {
  asm volatile(
      "mma.sync.aligned.m16n8k16.row.col.f32.bf16.bf16.f32 "
      "{%0,%1,%2,%3}, {%4,%5,%6,%7}, {%8,%9}, {%0,%1,%2,%3};"
      : "+f"(c[0]), "+f"(c[1]), "+f"(c[2]), "+f"(c[3])
      : "r"(a[0]), "r"(a[1]), "r"(a[2]), "r"(a[3]), "r"(b[0]), "r"(b[1]));
}
static __device__ __forceinline__ uint32_t cvt_bf16x2(float hi, float lo) {
  uint32_t r;
  asm("cvt.rn.bf16x2.f32 %0, %1, %2;" : "=r"(r) : "f"(hi), "f"(lo));
  return r;
}
// hi/lo split, 2 elems/cvt; bf16->f32 via exact bit-shift
static __device__ __forceinline__ void split8(const float* f, uint4& H,
                                              uint4& L) {
  uint32_t h[4], l[4];
#pragma unroll
  for (int j = 0; j < 4; ++j) {
    const float f0 = f[2 * j], f1 = f[2 * j + 1];
    const uint32_t hu = cvt_bf16x2(f1, f0);  // lo half = f0
    const float fh0 = __uint_as_float(hu << 16);
    const float fh1 = __uint_as_float(hu & 0xFFFF0000u);
    h[j] = hu;
    l[j] = cvt_bf16x2(f1 - fh1, f0 - fh0);
  }
  H = make_uint4(h[0], h[1], h[2], h[3]);
  L = make_uint4(l[0], l[1], l[2], l[3]);
}

// ---------------------------------------------------------------------------
// Pack: fp32 [rows,1024] -> SW128 bf16 hi/lo panels.
// grid (kb16, rb8, z32): z<16 -> enc panel (b=z); z>=16 -> dec panel (b=z-16)
// plus fused copy of dec into out[..., 0:1024].
// ---------------------------------------------------------------------------
__global__ __launch_bounds__(256) void conv_split_kernel(
    const float* __restrict__ enc, const float* __restrict__ dec,
    float* __restrict__ out) {
  const int kb = blockIdx.x, rb = blockIdx.y;
  const int which = blockIdx.z >> 4;
  const int b = blockIdx.z & 15;
  const float* src = which ? dec : enc;
  uint4* dh = which ? g_decPh : g_encPh;
  uint4* dl = which ? g_decPl : g_encPl;
  const size_t panel = ((size_t)(b * 8 + rb) * 16 + kb) * PANEL_U4;
  const float* sp = src + ((size_t)b * 1024 + rb * 128) * 1024 + kb * 64;
#pragma unroll
  for (int it = 0; it < 4; ++it) {
    const int chunk = it * 256 + threadIdx.x;
    const int r = chunk >> 3, cc = chunk & 7;
    const float4* s4 =
        reinterpret_cast<const float4*>(sp + (size_t)r * 1024 + cc * 8);
    float4 x0 = s4[0], x1 = s4[1];
    float f[8] = {x0.x, x0.y, x0.z, x0.w, x1.x, x1.y, x1.z, x1.w};
    uint4 H, L;
    split8(f, H, L);
    const uint32_t off = swz((uint32_t)(r * 128 + cc * 16)) >> 4;
    dh[panel + off] = H;
    dl[panel + off] = L;
    if (which) {
      float4* o4 = reinterpret_cast<float4*>(
          out + ((size_t)(b * 1024 + rb * 128 + r)) * 2048 + kb * 64 + cc * 8);
      o4[0] = x0;
      o4[1] = x1;
    }
  }
}

// ---------------------------------------------------------------------------
// Row softmax of S'[t,e] + bf16 hi/lo pack to attn' panels [t-rowblk][e-kblk].
// One warp per t-row. grid (128, b=16), block 256 (8 warps = 8 rows).
// ---------------------------------------------------------------------------
__global__ __launch_bounds__(256) void softmax_pack_kernel() {
  const int b = blockIdx.y;
  const int t = blockIdx.x * 8 + (threadIdx.x >> 5);
  const int lane = threadIdx.x & 31;
  const float* Sr = g_S + ((size_t)b * 1024 + t) * 1024;

  float f[4][8];
  float m = -3.402823466e38f;
#pragma unroll
  for (int i = 0; i < 4; ++i) {
    const float4* p = reinterpret_cast<const float4*>(Sr + i * 256 + lane * 8);
    const float4 x0 = p[0], x1 = p[1];
    f[i][0] = x0.x; f[i][1] = x0.y; f[i][2] = x0.z; f[i][3] = x0.w;
    f[i][4] = x1.x; f[i][5] = x1.y; f[i][6] = x1.z; f[i][7] = x1.w;
#pragma unroll
    for (int j = 0; j < 8; ++j) m = fmaxf(m, f[i][j]);
  }
#pragma unroll
  for (int o = 16; o; o >>= 1)
    m = fmaxf(m, __shfl_xor_sync(0xffffffffu, m, o));

  float s = 0.f;
#pragma unroll
  for (int i = 0; i < 4; ++i)
#pragma unroll
    for (int j = 0; j < 8; ++j) {
      f[i][j] = __expf(f[i][j] - m);
      s += f[i][j];
    }
#pragma unroll
  for (int o = 16; o; o >>= 1) s += __shfl_xor_sync(0xffffffffu, s, o);
  const float inv = 1.f / s;

  const int tb = t >> 7, tl = t & 127;
  const uint32_t off = swz((uint32_t)(tl * 128 + (lane & 7) * 16)) >> 4;
#pragma unroll
  for (int i = 0; i < 4; ++i) {
#pragma unroll
    for (int j = 0; j < 8; ++j) f[i][j] *= inv;
    uint4 H, L;
    split8(f[i], H, L);
    const int eb = i * 4 + (lane >> 3);
    const size_t panel = ((size_t)(b * 8 + tb) * 16 + eb) * PANEL_U4;
    g_attTh[panel + off] = H;
    g_attTl[panel + off] = L;
  }
}

// ---------------------------------------------------------------------------
// HMMA GEMM: C tile 128(M) x 64(N) fp32, K=1024, bf16 hi/lo split (3 MMAs).
// grid (nbk=16, mbk=8, b=16), 256 threads (8 warps: 4 m x 2 n, warp 32x32),
// BK=64, 2-stage cp.async pipeline, loads interleaved across kk sub-blocks,
// 48KB/stage => 96KB => 2 CTAs/SM.
// WHICH=0: GEMM1 decP x encP -> g_S (S'[t,e])   (B non-trans, [n,k] panels)
// WHICH=1: GEMM2 attT x encP -> out ctx         (B via ldmatrix.trans)
// ---------------------------------------------------------------------------
template <int WHICH>
__global__ __launch_bounds__(256, 2) void hmma_gemm_kernel(
    float* __restrict__ o) {
  extern __shared__ __align__(16) char dsm[];
  const uint4* Ah = WHICH ? g_attTh : g_decPh;
  const uint4* Al = WHICH ? g_attTl : g_decPl;
  const uint4* Bh = g_encPh;
  const uint4* Bl = g_encPl;
  float* C;
  int ldc, coff;
  size_t bstride;
  if (WHICH == 0) {
    C = g_S; ldc = 1024; coff = 0; bstride = (size_t)1024 * 1024;
  } else {
    C = o; ldc = 2048; coff = 1024; bstride = (size_t)1024 * 2048;
  }

  const int tid = threadIdx.x;
  const int wid = tid >> 5, lane = tid & 31;
  const int wm = wid & 3, wn = wid >> 2;  // warp tile: rows wm*32, cols wn*32
  const int b = blockIdx.z, mbk = blockIdx.y, nbk = blockIdx.x;
  const size_t apan = ((size_t)(b * 8 + mbk)) * 16;
  const uint32_t smem_base = smem_u32(dsm);

  // stage layout: Ah 0..16K, Al 16K..32K, Bh 32K..40K, Bl 40K..48K
  // issue one quarter of a chunk's loads (3 cp.async per thread)
  auto issue_part = [&](int c, int j) {
    const uint32_t base = smem_base + (uint32_t)(c & 1) * 49152u;
    const uint4* a0 = Ah + (apan + c) * PANEL_U4;
    const uint4* a1 = Al + (apan + c) * PANEL_U4;
    const int i = tid + j * 256;
    cp_async16(base + (uint32_t)i * 16u, a0 + i);
    cp_async16(base + 16384u + (uint32_t)i * 16u, a1 + i);
    if (j < 2) {
      size_t bpan;
      int brow0;
      if (WHICH == 0) {
        bpan = ((size_t)(b * 8 + (nbk >> 1)) * 16 + c) * PANEL_U4;
        brow0 = (nbk & 1) * 64;
      } else {
        bpan = ((size_t)(b * 8 + (c >> 1)) * 16 + nbk) * PANEL_U4;
        brow0 = (c & 1) * 64;
      }
      const int lu = tid + j * 256;
      const int prow = brow0 + (lu >> 3), uin = lu & 7;
      cp_async16(base + 32768u + (uint32_t)lu * 16u, Bh + bpan + prow * 8 + uin);
      cp_async16(base + 40960u + (uint32_t)lu * 16u, Bl + bpan + prow * 8 + uin);
    }
  };

  float acc[2][4][4];
#pragma unroll
  for (int mt = 0; mt < 2; ++mt)
#pragma unroll
    for (int nt = 0; nt < 4; ++nt)
#pragma unroll
      for (int j = 0; j < 4; ++j) acc[mt][nt][j] = 0.f;

#pragma unroll
  for (int j = 0; j < 4; ++j) issue_part(0, j);
  asm volatile("cp.async.commit_group;" ::: "memory");

  const uint32_t a_row = (uint32_t)(wm * 32 + (lane & 15));
  const uint32_t a_koff = (lane & 16) ? 16u : 0u;
  const uint32_t b_row =
      (uint32_t)(wn * 32 + (lane & 7) + ((lane & 16) ? 8 : 0));
  const uint32_t b_koff = (lane & 8) ? 16u : 0u;
  const uint32_t bt_krow = (uint32_t)(lane & 15);
  const uint32_t bt_coff = (uint32_t)(wn * 32 + ((lane & 16) ? 8 : 0)) * 2u;

  for (int c = 0; c < 16; ++c) {
    asm volatile("cp.async.wait_group 0;" ::: "memory");
    __syncthreads();

    const uint32_t sb = smem_base + (uint32_t)(c & 1) * 49152u;
    const uint32_t Ah_b = sb, Al_b = sb + 16384u;
    const uint32_t Bh_b = sb + 32768u, Bl_b = sb + 40960u;

#pragma unroll
    for (int kk = 0; kk < 4; ++kk) {
      uint32_t ah[2][4], al[2][4];
#pragma unroll
      for (int mt = 0; mt < 2; ++mt) {
        const uint32_t byte = swz((a_row + (uint32_t)mt * 16u) * 128u +
                                  (uint32_t)kk * 32u + a_koff);
        ldsm4(ah[mt], Ah_b + byte);
        ldsm4(al[mt], Al_b + byte);
      }
      uint32_t bh[2][4], bl[2][4];
#pragma unroll
      for (int np = 0; np < 2; ++np) {
        if (WHICH == 0) {
          const uint32_t byte = swz((b_row + (uint32_t)np * 16u) * 128u +
                                    (uint32_t)kk * 32u + b_koff);
          ldsm4(bh[np], Bh_b + byte);
          ldsm4(bl[np], Bl_b + byte);
        } else {
          const uint32_t byte =
              swz(((uint32_t)kk * 16u + bt_krow) * 128u + bt_coff +
                  (uint32_t)np * 32u);
          ldsm4t(bh[np], Bh_b + byte);
          ldsm4t(bl[np], Bl_b + byte);
        }
      }
      // interleave next-chunk load issue with compute (buffer (c+1)&1 was
      // consumed at iter c-1; the barrier above covers it)
      if (c + 1 < 16) issue_part(c + 1, kk);
#pragma unroll
      for (int mt = 0; mt < 2; ++mt)
#pragma unroll
        for (int nt = 0; nt < 4; ++nt) {
          const uint32_t* B0 = &bh[nt >> 1][(nt & 1) * 2];
          const uint32_t* B1 = &bl[nt >> 1][(nt & 1) * 2];
          mma16816(acc[mt][nt], ah[mt], B0);
          mma16816(acc[mt][nt], ah[mt], B1);
          mma16816(acc[mt][nt], al[mt], B0);
        }
    }
    asm volatile("cp.async.commit_group;" ::: "memory");
  }

  float* Cb = C + (size_t)b * bstride + (size_t)(mbk * 128) * ldc + coff +
              nbk * 64;
  const int g = lane >> 2, tig = lane & 3;
#pragma unroll
  for (int mt = 0; mt < 2; ++mt)
#pragma unroll
    for (int nt = 0; nt < 4; ++nt) {
      const int row = wm * 32 + mt * 16 + g;
      const int col = wn * 32 + nt * 8 + tig * 2;
      *reinterpret_cast<float2*>(Cb + (size_t)row * ldc + col) =
          make_float2(acc[mt][nt][0], acc[mt][nt][1]);
      *reinterpret_cast<float2*>(Cb + (size_t)(row + 8) * ldc + col) =
          make_float2(acc[mt][nt][2], acc[mt][nt][3]);
    }
}

// ---------------------------------------------------------------------------
extern "C" void kernel_launch(void* const* d_in, const int* in_sizes, int n_in,
                              void* d_out, int out_size) {
  const float* enc = (const float*)d_in[0];
  const float* dec = (const float*)d_in[1];
  float* out = (float*)d_out;

  cudaFuncSetAttribute(hmma_gemm_kernel<0>,
                       cudaFuncAttributeMaxDynamicSharedMemorySize, 98304);
  cudaFuncSetAttribute(hmma_gemm_kernel<1>,
                       cudaFuncAttributeMaxDynamicSharedMemorySize, 98304);

  dim3 cg(16, 8, 32);
  conv_split_kernel<<<cg, 256>>>(enc, dec, out);

  dim3 gg(16, 8, 16);
  hmma_gemm_kernel<0><<<gg, 256, 98304>>>(out);

  softmax_pack_kernel<<<dim3(128, 16), 256>>>();

  hmma_gemm_kernel<1><<<gg, 256, 98304>>>(out);
}

// round 11
// speedup vs baseline: 3.8957x; 1.3208x over previous
#include <cuda_runtime.h>
#include <cuda_bf16.h>
#include <cuda_fp16.h>
#include <cstdint>

// B=16, Te=1024, Td=1024, D=1024
//   S'[b,t,e]  = dec[b,t,:] . enc[b,e,:]     (GEMM1, bf16 hi/lo 3-MMA split)
//   A'[t,e]    = row-softmax_e(S')           (contiguous softmax, fp16 pack)
//   ctx[b,t,d] = sum_e A'[t,e] enc[e,d]      (GEMM2, single fp16 MMA)
//   out        = concat(dec, ctx)            [B, Td, 2048]

#define PANEL_U4 1024  // one 128x64 x 2B SW128 panel = 16KB = 1024 uint4
#define NPANEL 2048    // 16 b * 8 rowblk * 16 kblk

__device__ float g_S[(size_t)16 * 1024 * 1024];  // fp32 scores S'[t,e]
__device__ uint4 g_encPh[NPANEL * PANEL_U4], g_encPl[NPANEL * PANEL_U4];  // enc bf16 h/l
__device__ uint4 g_decPh[NPANEL * PANEL_U4], g_decPl[NPANEL * PANEL_U4];  // dec bf16 h/l
__device__ uint4 g_encH[NPANEL * PANEL_U4];  // enc fp16 [e,d]
__device__ uint4 g_attH[NPANEL * PANEL_U4];  // attn fp16 [t,e]

// ---------------------------------------------------------------------------
static __device__ __forceinline__ uint32_t smem_u32(const void* p) {
  uint32_t a;
  asm("{ .reg .u64 t; cvta.to.shared.u64 t, %1; cvt.u32.u64 %0, t; }"
      : "=r"(a) : "l"(p));
  return a;
}
static __device__ __forceinline__ uint32_t swz(uint32_t x) {
  return x ^ ((x >> 3) & 0x70);
}
static __device__ __forceinline__ void cp_async16(uint32_t dst,
                                                  const void* src) {
  asm volatile("cp.async.cg.shared.global [%0], [%1], 16;"
               :: "r"(dst), "l"(src) : "memory");
}
static __device__ __forceinline__ void ldsm4(uint32_t* r, uint32_t addr) {
  asm volatile(
      "ldmatrix.sync.aligned.m8n8.x4.shared.b16 {%0,%1,%2,%3}, [%4];"
      : "=r"(r[0]), "=r"(r[1]), "=r"(r[2]), "=r"(r[3])
      : "r"(addr));
}
static __device__ __forceinline__ void ldsm4t(uint32_t* r, uint32_t addr) {
  asm volatile(
      "ldmatrix.sync.aligned.m8n8.x4.trans.shared.b16 {%0,%1,%2,%3}, [%4];"
      : "=r"(r[0]), "=r"(r[1]), "=r"(r[2]), "=r"(r[3])
      : "r"(addr));
}
static __device__ __forceinline__ void mma16816(float* c, const uint32_t* a,
                                                const uint32_t* b) {
  asm volatile(
      "mma.sync.aligned.m16n8k16.row.col.f32.bf16.bf16.f32 "
      "{%0,%1,%2,%3}, {%4,%5,%6,%7}, {%8,%9}, {%0,%1,%2,%3};"
      : "+f"(c[0]), "+f"(c[1]), "+f"(c[2]), "+f"(c[3])
      : "r"(a[0]), "r"(a[1]), "r"(a[2]), "r"(a[3]), "r"(b[0]), "r"(b[1]));
}
static __device__ __forceinline__ void mma16816h(float* c, const uint32_t* a,
                                                 const uint32_t* b) {
  asm volatile(
      "mma.sync.aligned.m16n8k16.row.col.f32.f16.f16.f32 "
      "{%0,%1,%2,%3}, {%4,%5,%6,%7}, {%8,%9}, {%0,%1,%2,%3};"
      : "+f"(c[0]), "+f"(c[1]), "+f"(c[2]), "+f"(c[3])
      : "r"(a[0]), "r"(a[1]), "r"(a[2]), "r"(a[3]), "r"(b[0]), "r"(b[1]));
}
static __device__ __forceinline__ uint32_t cvt_bf16x2(float hi, float lo) {
  uint32_t r;
  asm("cvt.rn.bf16x2.f32 %0, %1, %2;" : "=r"(r) : "f"(hi), "f"(lo));
  return r;
}
// bf16 hi/lo split, 2 elems/cvt
static __device__ __forceinline__ void split8(const float* f, uint4& H,
                                              uint4& L) {
  uint32_t h[4], l[4];
#pragma unroll
  for (int j = 0; j < 4; ++j) {
    const float f0 = f[2 * j], f1 = f[2 * j + 1];
    const uint32_t hu = cvt_bf16x2(f1, f0);  // lo half = f0
    const float fh0 = __uint_as_float(hu << 16);
    const float fh1 = __uint_as_float(hu & 0xFFFF0000u);
    h[j] = hu;
    l[j] = cvt_bf16x2(f1 - fh1, f0 - fh0);
  }
  H = make_uint4(h[0], h[1], h[2], h[3]);
  L = make_uint4(l[0], l[1], l[2], l[3]);
}
// fp16 pack of 8 floats
static __device__ __forceinline__ uint4 pack8h(const float* f) {
  uint32_t u[4];
#pragma unroll
  for (int j = 0; j < 4; ++j) {
    const __half2 h = __floats2half2_rn(f[2 * j], f[2 * j + 1]);
    u[j] = *reinterpret_cast<const uint32_t*>(&h);
  }
  return make_uint4(u[0], u[1], u[2], u[3]);
}

// ---------------------------------------------------------------------------
// Pack: fp32 [rows,1024] -> SW128 panels.
// grid (kb16, rb8, z32): z<16 -> enc (bf16 h/l + fp16); z>=16 -> dec (bf16 h/l)
// plus fused copy of dec into out[..., 0:1024].
// ---------------------------------------------------------------------------
__global__ __launch_bounds__(256) void conv_split_kernel(
    const float* __restrict__ enc, const float* __restrict__ dec,
    float* __restrict__ out) {
  const int kb = blockIdx.x, rb = blockIdx.y;
  const int which = blockIdx.z >> 4;
  const int b = blockIdx.z & 15;
  const float* src = which ? dec : enc;
  uint4* dh = which ? g_decPh : g_encPh;
  uint4* dl = which ? g_decPl : g_encPl;
  const size_t panel = ((size_t)(b * 8 + rb) * 16 + kb) * PANEL_U4;
  const float* sp = src + ((size_t)b * 1024 + rb * 128) * 1024 + kb * 64;
#pragma unroll
  for (int it = 0; it < 4; ++it) {
    const int chunk = it * 256 + threadIdx.x;
    const int r = chunk >> 3, cc = chunk & 7;
    const float4* s4 =
        reinterpret_cast<const float4*>(sp + (size_t)r * 1024 + cc * 8);
    float4 x0 = s4[0], x1 = s4[1];
    float f[8] = {x0.x, x0.y, x0.z, x0.w, x1.x, x1.y, x1.z, x1.w};
    uint4 H, L;
    split8(f, H, L);
    const uint32_t off = swz((uint32_t)(r * 128 + cc * 16)) >> 4;
    dh[panel + off] = H;
    dl[panel + off] = L;
    if (which) {
      float4* o4 = reinterpret_cast<float4*>(
          out + ((size_t)(b * 1024 + rb * 128 + r)) * 2048 + kb * 64 + cc * 8);
      o4[0] = x0;
      o4[1] = x1;
    } else {
      g_encH[panel + off] = pack8h(f);
    }
  }
}

// ---------------------------------------------------------------------------
// Row softmax of S'[t,e] + fp16 pack to attn panels [t-rowblk][e-kblk].
// One warp per t-row. grid (128, b=16), block 256 (8 warps = 8 rows).
// ---------------------------------------------------------------------------
__global__ __launch_bounds__(256) void softmax_pack_kernel() {
  const int b = blockIdx.y;
  const int t = blockIdx.x * 8 + (threadIdx.x >> 5);
  const int lane = threadIdx.x & 31;
  const float* Sr = g_S + ((size_t)b * 1024 + t) * 1024;

  float f[4][8];
  float m = -3.402823466e38f;
#pragma unroll
  for (int i = 0; i < 4; ++i) {
    const float4* p = reinterpret_cast<const float4*>(Sr + i * 256 + lane * 8);
    const float4 x0 = p[0], x1 = p[1];
    f[i][0] = x0.x; f[i][1] = x0.y; f[i][2] = x0.z; f[i][3] = x0.w;
    f[i][4] = x1.x; f[i][5] = x1.y; f[i][6] = x1.z; f[i][7] = x1.w;
#pragma unroll
    for (int j = 0; j < 8; ++j) m = fmaxf(m, f[i][j]);
  }
#pragma unroll
  for (int o = 16; o; o >>= 1)
    m = fmaxf(m, __shfl_xor_sync(0xffffffffu, m, o));

  float s = 0.f;
#pragma unroll
  for (int i = 0; i < 4; ++i)
#pragma unroll
    for (int j = 0; j < 8; ++j) {
      f[i][j] = __expf(f[i][j] - m);
      s += f[i][j];
    }
#pragma unroll
  for (int o = 16; o; o >>= 1) s += __shfl_xor_sync(0xffffffffu, s, o);
  const float inv = 1.f / s;

  const int tb = t >> 7, tl = t & 127;
  const uint32_t off = swz((uint32_t)(tl * 128 + (lane & 7) * 16)) >> 4;
#pragma unroll
  for (int i = 0; i < 4; ++i) {
#pragma unroll
    for (int j = 0; j < 8; ++j) f[i][j] *= inv;
    const int eb = i * 4 + (lane >> 3);
    const size_t panel = ((size_t)(b * 8 + tb) * 16 + eb) * PANEL_U4;
    g_attH[panel + off] = pack8h(f[i]);
  }
}

// ---------------------------------------------------------------------------
// GEMM1: S'[t,e] = dec . enc^T, bf16 hi/lo split (3 MMAs), C tile 128x64,
// K=1024, BK=64, 2-stage cp.async (interleaved issue), 48KB/stage, 2 CTAs/SM.
// grid (nbk=16, mbk=8, b=16), 256 threads (8 warps: 4m x 2n, warp 32x32).
// ---------------------------------------------------------------------------
__global__ __launch_bounds__(256, 2) void hmma_gemm1_kernel() {
  extern __shared__ __align__(16) char dsm[];
  const int tid = threadIdx.x;
  const int wid = tid >> 5, lane = tid & 31;
  const int wm = wid & 3, wn = wid >> 2;
  const int b = blockIdx.z, mbk = blockIdx.y, nbk = blockIdx.x;
  const size_t apan = ((size_t)(b * 8 + mbk)) * 16;
  const uint32_t smem_base = smem_u32(dsm);

  auto issue_part = [&](int c, int j) {
    const uint32_t base = smem_base + (uint32_t)(c & 1) * 49152u;
    const uint4* a0 = g_decPh + (apan + c) * PANEL_U4;
    const uint4* a1 = g_decPl + (apan + c) * PANEL_U4;
    const int i = tid + j * 256;
    cp_async16(base + (uint32_t)i * 16u, a0 + i);
    cp_async16(base + 16384u + (uint32_t)i * 16u, a1 + i);
    if (j < 2) {
      const size_t bpan = ((size_t)(b * 8 + (nbk >> 1)) * 16 + c) * PANEL_U4;
      const int brow0 = (nbk & 1) * 64;
      const int lu = tid + j * 256;
      const int prow = brow0 + (lu >> 3), uin = lu & 7;
      cp_async16(base + 32768u + (uint32_t)lu * 16u,
                 g_encPh + bpan + prow * 8 + uin);
      cp_async16(base + 40960u + (uint32_t)lu * 16u,
                 g_encPl + bpan + prow * 8 + uin);
    }
  };

  float acc[2][4][4];
#pragma unroll
  for (int mt = 0; mt < 2; ++mt)
#pragma unroll
    for (int nt = 0; nt < 4; ++nt)
#pragma unroll
      for (int j = 0; j < 4; ++j) acc[mt][nt][j] = 0.f;

#pragma unroll
  for (int j = 0; j < 4; ++j) issue_part(0, j);
  asm volatile("cp.async.commit_group;" ::: "memory");

  const uint32_t a_row = (uint32_t)(wm * 32 + (lane & 15));
  const uint32_t a_koff = (lane & 16) ? 16u : 0u;
  const uint32_t b_row =
      (uint32_t)(wn * 32 + (lane & 7) + ((lane & 16) ? 8 : 0));
  const uint32_t b_koff = (lane & 8) ? 16u : 0u;

  for (int c = 0; c < 16; ++c) {
    asm volatile("cp.async.wait_group 0;" ::: "memory");
    __syncthreads();
    const uint32_t sb = smem_base + (uint32_t)(c & 1) * 49152u;
    const uint32_t Ah_b = sb, Al_b = sb + 16384u;
    const uint32_t Bh_b = sb + 32768u, Bl_b = sb + 40960u;

#pragma unroll
    for (int kk = 0; kk < 4; ++kk) {
      uint32_t ah[2][4], al[2][4];
#pragma unroll
      for (int mt = 0; mt < 2; ++mt) {
        const uint32_t byte = swz((a_row + (uint32_t)mt * 16u) * 128u +
                                  (uint32_t)kk * 32u + a_koff);
        ldsm4(ah[mt], Ah_b + byte);
        ldsm4(al[mt], Al_b + byte);
      }
      uint32_t bh[2][4], bl[2][4];
#pragma unroll
      for (int np = 0; np < 2; ++np) {
        const uint32_t byte = swz((b_row + (uint32_t)np * 16u) * 128u +
                                  (uint32_t)kk * 32u + b_koff);
        ldsm4(bh[np], Bh_b + byte);
        ldsm4(bl[np], Bl_b + byte);
      }
      if (c + 1 < 16) issue_part(c + 1, kk);
#pragma unroll
      for (int mt = 0; mt < 2; ++mt)
#pragma unroll
        for (int nt = 0; nt < 4; ++nt) {
          const uint32_t* B0 = &bh[nt >> 1][(nt & 1) * 2];
          const uint32_t* B1 = &bl[nt >> 1][(nt & 1) * 2];
          mma16816(acc[mt][nt], ah[mt], B0);
          mma16816(acc[mt][nt], ah[mt], B1);
          mma16816(acc[mt][nt], al[mt], B0);
        }
    }
    asm volatile("cp.async.commit_group;" ::: "memory");
  }

  float* Cb = g_S + (size_t)b * 1024 * 1024 + (size_t)(mbk * 128) * 1024 +
              nbk * 64;
  const int g = lane >> 2, tig = lane & 3;
#pragma unroll
  for (int mt = 0; mt < 2; ++mt)
#pragma unroll
    for (int nt = 0; nt < 4; ++nt) {
      const int row = wm * 32 + mt * 16 + g;
      const int col = wn * 32 + nt * 8 + tig * 2;
      *reinterpret_cast<float2*>(Cb + (size_t)row * 1024 + col) =
          make_float2(acc[mt][nt][0], acc[mt][nt][1]);
      *reinterpret_cast<float2*>(Cb + (size_t)(row + 8) * 1024 + col) =
          make_float2(acc[mt][nt][2], acc[mt][nt][3]);
    }
}

// ---------------------------------------------------------------------------
// GEMM2: ctx[t,d] = attn . enc, SINGLE fp16 MMA (fp32 accumulate).
// A = g_attH [t,e] panels (non-trans), B = g_encH [e,d] via ldmatrix.trans.
// C tile 128x64, BK=64, 2-stage cp.async, 24KB/stage, 3 CTAs/SM.
// grid (nbk=16, mbk=8, b=16), 256 threads (8 warps: 4m x 2n, warp 32x32).
// ---------------------------------------------------------------------------
__global__ __launch_bounds__(256, 3) void hmma_gemm2_kernel(
    float* __restrict__ o) {
  extern __shared__ __align__(16) char dsm[];
  const int tid = threadIdx.x;
  const int wid = tid >> 5, lane = tid & 31;
  const int wm = wid & 3, wn = wid >> 2;
  const int b = blockIdx.z, mbk = blockIdx.y, nbk = blockIdx.x;
  const size_t apan = ((size_t)(b * 8 + mbk)) * 16;
  const uint32_t smem_base = smem_u32(dsm);

  // stage: A 0..16K, B 16K..24K; stage stride 24576
  auto issue_part = [&](int c, int j) {
    const uint32_t base = smem_base + (uint32_t)(c & 1) * 24576u;
    const uint4* a0 = g_attH + (apan + c) * PANEL_U4;
    const int i = tid + j * 256;
    cp_async16(base + (uint32_t)i * 16u, a0 + i);
    if (j < 2) {
      const size_t bpan = ((size_t)(b * 8 + (c >> 1)) * 16 + nbk) * PANEL_U4;
      const int brow0 = (c & 1) * 64;
      const int lu = tid + j * 256;
      const int prow = brow0 + (lu >> 3), uin = lu & 7;
      cp_async16(base + 16384u + (uint32_t)lu * 16u,
                 g_encH + bpan + prow * 8 + uin);
    }
  };

  float acc[2][4][4];
#pragma unroll
  for (int mt = 0; mt < 2; ++mt)
#pragma unroll
    for (int nt = 0; nt < 4; ++nt)
#pragma unroll
      for (int j = 0; j < 4; ++j) acc[mt][nt][j] = 0.f;

#pragma unroll
  for (int j = 0; j < 4; ++j) issue_part(0, j);
  asm volatile("cp.async.commit_group;" ::: "memory");

  const uint32_t a_row = (uint32_t)(wm * 32 + (lane & 15));
  const uint32_t a_koff = (lane & 16) ? 16u : 0u;
  const uint32_t bt_krow = (uint32_t)(lane & 15);
  const uint32_t bt_coff = (uint32_t)(wn * 32 + ((lane & 16) ? 8 : 0)) * 2u;

  for (int c = 0; c < 16; ++c) {
    asm volatile("cp.async.wait_group 0;" ::: "memory");
    __syncthreads();
    const uint32_t sb = smem_base + (uint32_t)(c & 1) * 24576u;
    const uint32_t A_b = sb, B_b = sb + 16384u;

#pragma unroll
    for (int kk = 0; kk < 4; ++kk) {
      uint32_t a[2][4];
#pragma unroll
      for (int mt = 0; mt < 2; ++mt) {
        const uint32_t byte = swz((a_row + (uint32_t)mt * 16u) * 128u +
                                  (uint32_t)kk * 32u + a_koff);
        ldsm4(a[mt], A_b + byte);
      }
      uint32_t bv[2][4];
#pragma unroll
      for (int np = 0; np < 2; ++np) {
        const uint32_t byte = swz(((uint32_t)kk * 16u + bt_krow) * 128u +
                                  bt_coff + (uint32_t)np * 32u);
        ldsm4t(bv[np], B_b + byte);
      }
      if (c + 1 < 16) issue_part(c + 1, kk);
#pragma unroll
      for (int mt = 0; mt < 2; ++mt)
#pragma unroll
        for (int nt = 0; nt < 4; ++nt)
          mma16816h(acc[mt][nt], a[mt], &bv[nt >> 1][(nt & 1) * 2]);
    }
    asm volatile("cp.async.commit_group;" ::: "memory");
  }

  float* Cb = o + (size_t)b * 1024 * 2048 + (size_t)(mbk * 128) * 2048 + 1024 +
              nbk * 64;
  const int g = lane >> 2, tig = lane & 3;
#pragma unroll
  for (int mt = 0; mt < 2; ++mt)
#pragma unroll
    for (int nt = 0; nt < 4; ++nt) {
      const int row = wm * 32 + mt * 16 + g;
      const int col = wn * 32 + nt * 8 + tig * 2;
      *reinterpret_cast<float2*>(Cb + (size_t)row * 2048 + col) =
          make_float2(acc[mt][nt][0], acc[mt][nt][1]);
      *reinterpret_cast<float2*>(Cb + (size_t)(row + 8) * 2048 + col) =
          make_float2(acc[mt][nt][2], acc[mt][nt][3]);
    }
}

// ---------------------------------------------------------------------------
extern "C" void kernel_launch(void* const* d_in, const int* in_sizes, int n_in,
                              void* d_out, int out_size) {
  const float* enc = (const float*)d_in[0];
  const float* dec = (const float*)d_in[1];
  float* out = (float*)d_out;

  cudaFuncSetAttribute(hmma_gemm1_kernel,
                       cudaFuncAttributeMaxDynamicSharedMemorySize, 98304);
  cudaFuncSetAttribute(hmma_gemm2_kernel,
                       cudaFuncAttributeMaxDynamicSharedMemorySize, 49152);

  dim3 cg(16, 8, 32);
  conv_split_kernel<<<cg, 256>>>(enc, dec, out);

  dim3 gg(16, 8, 16);
  hmma_gemm1_kernel<<<gg, 256, 98304>>>();

  softmax_pack_kernel<<<dim3(128, 16), 256>>>();

  hmma_gemm2_kernel<<<gg, 256, 49152>>>(out);
}

// round 12
// speedup vs baseline: 3.9121x; 1.0042x over previous
#include <cuda_runtime.h>
#include <cuda_bf16.h>
#include <cuda_fp16.h>
#include <cstdint>

// B=16, Te=1024, Td=1024, D=1024
//   S'[b,t,e]  = dec[b,t,:] . enc[b,e,:]     (GEMM1, bf16 hi/lo 3-MMA split)
//   A'[t,e]    = row-softmax_e(S')           (contiguous softmax, fp16 pack)
//   ctx[b,t,d] = sum_e A'[t,e] enc[e,d]      (GEMM2, single fp16 MMA)
//   out        = concat(dec, ctx)            [B, Td, 2048]

#define PANEL_U4 1024  // one 128x64 x 2B SW128 panel = 16KB = 1024 uint4
#define NPANEL 2048    // 16 b * 8 rowblk * 16 kblk

__device__ float g_S[(size_t)16 * 1024 * 1024];  // fp32 scores S'[t,e]
__device__ uint4 g_encPh[NPANEL * PANEL_U4], g_encPl[NPANEL * PANEL_U4];  // enc bf16 h/l
__device__ uint4 g_decPh[NPANEL * PANEL_U4], g_decPl[NPANEL * PANEL_U4];  // dec bf16 h/l
__device__ uint4 g_encH[NPANEL * PANEL_U4];  // enc fp16 [e,d]
__device__ uint4 g_attH[NPANEL * PANEL_U4];  // attn fp16 [t,e]

// ---------------------------------------------------------------------------
static __device__ __forceinline__ uint32_t smem_u32(const void* p) {
  uint32_t a;
  asm("{ .reg .u64 t; cvta.to.shared.u64 t, %1; cvt.u32.u64 %0, t; }"
      : "=r"(a) : "l"(p));
  return a;
}
static __device__ __forceinline__ uint32_t swz(uint32_t x) {
  return x ^ ((x >> 3) & 0x70);
}
static __device__ __forceinline__ void cp_async16(uint32_t dst,
                                                  const void* src) {
  asm volatile("cp.async.cg.shared.global [%0], [%1], 16;"
               :: "r"(dst), "l"(src) : "memory");
}
static __device__ __forceinline__ void ldsm4(uint32_t* r, uint32_t addr) {
  asm volatile(
      "ldmatrix.sync.aligned.m8n8.x4.shared.b16 {%0,%1,%2,%3}, [%4];"
      : "=r"(r[0]), "=r"(r[1]), "=r"(r[2]), "=r"(r[3])
      : "r"(addr));
}
static __device__ __forceinline__ void ldsm4t(uint32_t* r, uint32_t addr) {
  asm volatile(
      "ldmatrix.sync.aligned.m8n8.x4.trans.shared.b16 {%0,%1,%2,%3}, [%4];"
      : "=r"(r[0]), "=r"(r[1]), "=r"(r[2]), "=r"(r[3])
      : "r"(addr));
}
static __device__ __forceinline__ void mma16816(float* c, const uint32_t* a,
                                                const uint32_t* b) {
  asm volatile(
      "mma.sync.aligned.m16n8k16.row.col.f32.bf16.bf16.f32 "
      "{%0,%1,%2,%3}, {%4,%5,%6,%7}, {%8,%9}, {%0,%1,%2,%3};"
      : "+f"(c[0]), "+f"(c[1]), "+f"(c[2]), "+f"(c[3])
      : "r"(a[0]), "r"(a[1]), "r"(a[2]), "r"(a[3]), "r"(b[0]), "r"(b[1]));
}
static __device__ __forceinline__ void mma16816h(float* c, const uint32_t* a,
                                                 const uint32_t* b) {
  asm volatile(
      "mma.sync.aligned.m16n8k16.row.col.f32.f16.f16.f32 "
      "{%0,%1,%2,%3}, {%4,%5,%6,%7}, {%8,%9}, {%0,%1,%2,%3};"
      : "+f"(c[0]), "+f"(c[1]), "+f"(c[2]), "+f"(c[3])
      : "r"(a[0]), "r"(a[1]), "r"(a[2]), "r"(a[3]), "r"(b[0]), "r"(b[1]));
}
static __device__ __forceinline__ uint32_t cvt_bf16x2(float hi, float lo) {
  uint32_t r;
  asm("cvt.rn.bf16x2.f32 %0, %1, %2;" : "=r"(r) : "f"(hi), "f"(lo));
  return r;
}
// bf16 hi/lo split, 2 elems/cvt
static __device__ __forceinline__ void split8(const float* f, uint4& H,
                                              uint4& L) {
  uint32_t h[4], l[4];
#pragma unroll
  for (int j = 0; j < 4; ++j) {
    const float f0 = f[2 * j], f1 = f[2 * j + 1];
    const uint32_t hu = cvt_bf16x2(f1, f0);  // lo half = f0
    const float fh0 = __uint_as_float(hu << 16);
    const float fh1 = __uint_as_float(hu & 0xFFFF0000u);
    h[j] = hu;
    l[j] = cvt_bf16x2(f1 - fh1, f0 - fh0);
  }
  H = make_uint4(h[0], h[1], h[2], h[3]);
  L = make_uint4(l[0], l[1], l[2], l[3]);
}
// fp16 pack of 8 floats
static __device__ __forceinline__ uint4 pack8h(const float* f) {
  uint32_t u[4];
#pragma unroll
  for (int j = 0; j < 4; ++j) {
    const __half2 h = __floats2half2_rn(f[2 * j], f[2 * j + 1]);
    u[j] = *reinterpret_cast<const uint32_t*>(&h);
  }
  return make_uint4(u[0], u[1], u[2], u[3]);
}

// ---------------------------------------------------------------------------
// Pack: fp32 [rows,1024] -> SW128 panels.
// grid (kb16, rb8, z32): z<16 -> enc (bf16 h/l + fp16); z>=16 -> dec (bf16 h/l)
// plus fused copy of dec into out[..., 0:1024].
// ---------------------------------------------------------------------------
__global__ __launch_bounds__(256) void conv_split_kernel(
    const float* __restrict__ enc, const float* __restrict__ dec,
    float* __restrict__ out) {
  const int kb = blockIdx.x, rb = blockIdx.y;
  const int which = blockIdx.z >> 4;
  const int b = blockIdx.z & 15;
  const float* src = which ? dec : enc;
  uint4* dh = which ? g_decPh : g_encPh;
  uint4* dl = which ? g_decPl : g_encPl;
  const size_t panel = ((size_t)(b * 8 + rb) * 16 + kb) * PANEL_U4;
  const float* sp = src + ((size_t)b * 1024 + rb * 128) * 1024 + kb * 64;
#pragma unroll
  for (int it = 0; it < 4; ++it) {
    const int chunk = it * 256 + threadIdx.x;
    const int r = chunk >> 3, cc = chunk & 7;
    const float4* s4 =
        reinterpret_cast<const float4*>(sp + (size_t)r * 1024 + cc * 8);
    float4 x0 = s4[0], x1 = s4[1];
    float f[8] = {x0.x, x0.y, x0.z, x0.w, x1.x, x1.y, x1.z, x1.w};
    uint4 H, L;
    split8(f, H, L);
    const uint32_t off = swz((uint32_t)(r * 128 + cc * 16)) >> 4;
    dh[panel + off] = H;
    dl[panel + off] = L;
    if (which) {
      float4* o4 = reinterpret_cast<float4*>(
          out + ((size_t)(b * 1024 + rb * 128 + r)) * 2048 + kb * 64 + cc * 8);
      o4[0] = x0;
      o4[1] = x1;
    } else {
      g_encH[panel + off] = pack8h(f);
    }
  }
}

// ---------------------------------------------------------------------------
// Row softmax of S'[t,e] + fp16 pack to attn panels [t-rowblk][e-kblk].
// One warp per t-row. grid (128, b=16), block 256 (8 warps = 8 rows).
// ---------------------------------------------------------------------------
__global__ __launch_bounds__(256) void softmax_pack_kernel() {
  const int b = blockIdx.y;
  const int t = blockIdx.x * 8 + (threadIdx.x >> 5);
  const int lane = threadIdx.x & 31;
  const float* Sr = g_S + ((size_t)b * 1024 + t) * 1024;

  float f[4][8];
  float m = -3.402823466e38f;
#pragma unroll
  for (int i = 0; i < 4; ++i) {
    const float4* p = reinterpret_cast<const float4*>(Sr + i * 256 + lane * 8);
    const float4 x0 = p[0], x1 = p[1];
    f[i][0] = x0.x; f[i][1] = x0.y; f[i][2] = x0.z; f[i][3] = x0.w;
    f[i][4] = x1.x; f[i][5] = x1.y; f[i][6] = x1.z; f[i][7] = x1.w;
#pragma unroll
    for (int j = 0; j < 8; ++j) m = fmaxf(m, f[i][j]);
  }
#pragma unroll
  for (int o = 16; o; o >>= 1)
    m = fmaxf(m, __shfl_xor_sync(0xffffffffu, m, o));

  float s = 0.f;
#pragma unroll
  for (int i = 0; i < 4; ++i)
#pragma unroll
    for (int j = 0; j < 8; ++j) {
      f[i][j] = __expf(f[i][j] - m);
      s += f[i][j];
    }
#pragma unroll
  for (int o = 16; o; o >>= 1) s += __shfl_xor_sync(0xffffffffu, s, o);
  const float inv = 1.f / s;

  const int tb = t >> 7, tl = t & 127;
  const uint32_t off = swz((uint32_t)(tl * 128 + (lane & 7) * 16)) >> 4;
#pragma unroll
  for (int i = 0; i < 4; ++i) {
#pragma unroll
    for (int j = 0; j < 8; ++j) f[i][j] *= inv;
    const int eb = i * 4 + (lane >> 3);
    const size_t panel = ((size_t)(b * 8 + tb) * 16 + eb) * PANEL_U4;
    g_attH[panel + off] = pack8h(f[i]);
  }
}

// ---------------------------------------------------------------------------
// GEMM1: S'[t,e] = dec . enc^T, bf16 hi/lo split (3 MMAs), C tile 128x64,
// K=1024, BK=64, 2-stage cp.async (interleaved issue), 48KB/stage, 2 CTAs/SM.
// grid (nbk=16, mbk=8, b=16), 256 threads (8 warps: 4m x 2n, warp 32x32).
// ---------------------------------------------------------------------------
__global__ __launch_bounds__(256, 2) void hmma_gemm1_kernel() {
  extern __shared__ __align__(16) char dsm[];
  const int tid = threadIdx.x;
  const int wid = tid >> 5, lane = tid & 31;
  const int wm = wid & 3, wn = wid >> 2;
  const int b = blockIdx.z, mbk = blockIdx.y, nbk = blockIdx.x;
  const size_t apan = ((size_t)(b * 8 + mbk)) * 16;
  const uint32_t smem_base = smem_u32(dsm);

  auto issue_part = [&](int c, int j) {
    const uint32_t base = smem_base + (uint32_t)(c & 1) * 49152u;
    const uint4* a0 = g_decPh + (apan + c) * PANEL_U4;
    const uint4* a1 = g_decPl + (apan + c) * PANEL_U4;
    const int i = tid + j * 256;
    cp_async16(base + (uint32_t)i * 16u, a0 + i);
    cp_async16(base + 16384u + (uint32_t)i * 16u, a1 + i);
    if (j < 2) {
      const size_t bpan = ((size_t)(b * 8 + (nbk >> 1)) * 16 + c) * PANEL_U4;
      const int brow0 = (nbk & 1) * 64;
      const int lu = tid + j * 256;
      const int prow = brow0 + (lu >> 3), uin = lu & 7;
      cp_async16(base + 32768u + (uint32_t)lu * 16u,
                 g_encPh + bpan + prow * 8 + uin);
      cp_async16(base + 40960u + (uint32_t)lu * 16u,
                 g_encPl + bpan + prow * 8 + uin);
    }
  };

  float acc[2][4][4];
#pragma unroll
  for (int mt = 0; mt < 2; ++mt)
#pragma unroll
    for (int nt = 0; nt < 4; ++nt)
#pragma unroll
      for (int j = 0; j < 4; ++j) acc[mt][nt][j] = 0.f;

#pragma unroll
  for (int j = 0; j < 4; ++j) issue_part(0, j);
  asm volatile("cp.async.commit_group;" ::: "memory");

  const uint32_t a_row = (uint32_t)(wm * 32 + (lane & 15));
  const uint32_t a_koff = (lane & 16) ? 16u : 0u;
  const uint32_t b_row =
      (uint32_t)(wn * 32 + (lane & 7) + ((lane & 16) ? 8 : 0));
  const uint32_t b_koff = (lane & 8) ? 16u : 0u;

  for (int c = 0; c < 16; ++c) {
    asm volatile("cp.async.wait_group 0;" ::: "memory");
    __syncthreads();
    const uint32_t sb = smem_base + (uint32_t)(c & 1) * 49152u;
    const uint32_t Ah_b = sb, Al_b = sb + 16384u;
    const uint32_t Bh_b = sb + 32768u, Bl_b = sb + 40960u;

#pragma unroll
    for (int kk = 0; kk < 4; ++kk) {
      uint32_t ah[2][4], al[2][4];
#pragma unroll
      for (int mt = 0; mt < 2; ++mt) {
        const uint32_t byte = swz((a_row + (uint32_t)mt * 16u) * 128u +
                                  (uint32_t)kk * 32u + a_koff);
        ldsm4(ah[mt], Ah_b + byte);
        ldsm4(al[mt], Al_b + byte);
      }
      uint32_t bh[2][4], bl[2][4];
#pragma unroll
      for (int np = 0; np < 2; ++np) {
        const uint32_t byte = swz((b_row + (uint32_t)np * 16u) * 128u +
                                  (uint32_t)kk * 32u + b_koff);
        ldsm4(bh[np], Bh_b + byte);
        ldsm4(bl[np], Bl_b + byte);
      }
      if (c + 1 < 16) issue_part(c + 1, kk);
#pragma unroll
      for (int mt = 0; mt < 2; ++mt)
#pragma unroll
        for (int nt = 0; nt < 4; ++nt) {
          const uint32_t* B0 = &bh[nt >> 1][(nt & 1) * 2];
          const uint32_t* B1 = &bl[nt >> 1][(nt & 1) * 2];
          mma16816(acc[mt][nt], ah[mt], B0);
          mma16816(acc[mt][nt], ah[mt], B1);
          mma16816(acc[mt][nt], al[mt], B0);
        }
    }
    asm volatile("cp.async.commit_group;" ::: "memory");
  }

  float* Cb = g_S + (size_t)b * 1024 * 1024 + (size_t)(mbk * 128) * 1024 +
              nbk * 64;
  const int g = lane >> 2, tig = lane & 3;
#pragma unroll
  for (int mt = 0; mt < 2; ++mt)
#pragma unroll
    for (int nt = 0; nt < 4; ++nt) {
      const int row = wm * 32 + mt * 16 + g;
      const int col = wn * 32 + nt * 8 + tig * 2;
      *reinterpret_cast<float2*>(Cb + (size_t)row * 1024 + col) =
          make_float2(acc[mt][nt][0], acc[mt][nt][1]);
      *reinterpret_cast<float2*>(Cb + (size_t)(row + 8) * 1024 + col) =
          make_float2(acc[mt][nt][2], acc[mt][nt][3]);
    }
}

// ---------------------------------------------------------------------------
// GEMM2: ctx[t,d] = attn . enc, SINGLE fp16 MMA (fp32 accumulate).
// C tile 128(M=t) x 128(N=d), warp tile 32x64 (8 warps: 4m x 2n).
// A = g_attH [t,e] panels (non-trans); B = g_encH [e,d] via ldmatrix.trans,
// two 64-col d-halves per chunk staged in separate 8KB blocks (one per n-warp).
// BK=64, 2-stage cp.async (32KB/stage => 64KB), 2 CTAs/SM.
// grid (nbk=8, mbk=8, b=16).
// ---------------------------------------------------------------------------
__global__ __launch_bounds__(256, 2) void hmma_gemm2_kernel(
    float* __restrict__ o) {
  extern __shared__ __align__(16) char dsm[];
  const int tid = threadIdx.x;
  const int wid = tid >> 5, lane = tid & 31;
  const int wm = wid & 3, wn = wid >> 2;
  const int b = blockIdx.z, mbk = blockIdx.y, nbk = blockIdx.x;
  const size_t apan = ((size_t)(b * 8 + mbk)) * 16;
  const uint32_t smem_base = smem_u32(dsm);

  // stage: A 0..16K, B 16K..32K ([dhalf 8KB][64 e-rows][128B]); stride 32768
  auto issue_part = [&](int c, int j) {
    const uint32_t base = smem_base + (uint32_t)(c & 1) * 32768u;
    const int i = tid + j * 256;
    cp_async16(base + (uint32_t)i * 16u, g_attH + (apan + c) * PANEL_U4 + i);
    // B: lu 0..1023 = dhalf*512 + r*8 + uin
    const int lu = i;
    const int dhalf = lu >> 9, r = (lu >> 3) & 63, uin = lu & 7;
    const size_t bpan =
        ((size_t)(b * 8 + (c >> 1)) * 16 + nbk * 2 + dhalf) * PANEL_U4;
    const int prow = (c & 1) * 64 + r;
    cp_async16(base + 16384u + (uint32_t)lu * 16u,
               g_encH + bpan + prow * 8 + uin);
  };

  float acc[2][8][4];
#pragma unroll
  for (int mt = 0; mt < 2; ++mt)
#pragma unroll
    for (int nt = 0; nt < 8; ++nt)
#pragma unroll
      for (int j = 0; j < 4; ++j) acc[mt][nt][j] = 0.f;

#pragma unroll
  for (int j = 0; j < 4; ++j) issue_part(0, j);
  asm volatile("cp.async.commit_group;" ::: "memory");

  const uint32_t a_row = (uint32_t)(wm * 32 + (lane & 15));
  const uint32_t a_koff = (lane & 16) ? 16u : 0u;
  const uint32_t bt_krow = (uint32_t)(lane & 15);
  const uint32_t bt_coff = (lane & 16) ? 16u : 0u;  // within 64-col dhalf

  for (int c = 0; c < 16; ++c) {
    asm volatile("cp.async.wait_group 0;" ::: "memory");
    __syncthreads();
    const uint32_t sb = smem_base + (uint32_t)(c & 1) * 32768u;
    const uint32_t A_b = sb;
    const uint32_t B_b = sb + 16384u + (uint32_t)wn * 8192u;  // this warp's dhalf

#pragma unroll
    for (int kk = 0; kk < 4; ++kk) {
      uint32_t a[2][4];
#pragma unroll
      for (int mt = 0; mt < 2; ++mt) {
        const uint32_t byte = swz((a_row + (uint32_t)mt * 16u) * 128u +
                                  (uint32_t)kk * 32u + a_koff);
        ldsm4(a[mt], A_b + byte);
      }
      uint32_t bv[4][4];
#pragma unroll
      for (int np = 0; np < 4; ++np) {
        const uint32_t byte = swz(((uint32_t)kk * 16u + bt_krow) * 128u +
                                  bt_coff + (uint32_t)np * 32u);
        ldsm4t(bv[np], B_b + byte);
      }
      if (c + 1 < 16) issue_part(c + 1, kk);
#pragma unroll
      for (int mt = 0; mt < 2; ++mt)
#pragma unroll
        for (int nt = 0; nt < 8; ++nt)
          mma16816h(acc[mt][nt], a[mt], &bv[nt >> 1][(nt & 1) * 2]);
    }
    asm volatile("cp.async.commit_group;" ::: "memory");
  }

  float* Cb = o + (size_t)b * 1024 * 2048 + (size_t)(mbk * 128) * 2048 + 1024 +
              nbk * 128;
  const int g = lane >> 2, tig = lane & 3;
#pragma unroll
  for (int mt = 0; mt < 2; ++mt)
#pragma unroll
    for (int nt = 0; nt < 8; ++nt) {
      const int row = wm * 32 + mt * 16 + g;
      const int col = wn * 64 + nt * 8 + tig * 2;
      *reinterpret_cast<float2*>(Cb + (size_t)row * 2048 + col) =
          make_float2(acc[mt][nt][0], acc[mt][nt][1]);
      *reinterpret_cast<float2*>(Cb + (size_t)(row + 8) * 2048 + col) =
          make_float2(acc[mt][nt][2], acc[mt][nt][3]);
    }
}

// ---------------------------------------------------------------------------
extern "C" void kernel_launch(void* const* d_in, const int* in_sizes, int n_in,
                              void* d_out, int out_size) {
  const float* enc = (const float*)d_in[0];
  const float* dec = (const float*)d_in[1];
  float* out = (float*)d_out;

  cudaFuncSetAttribute(hmma_gemm1_kernel,
                       cudaFuncAttributeMaxDynamicSharedMemorySize, 98304);
  cudaFuncSetAttribute(hmma_gemm2_kernel,
                       cudaFuncAttributeMaxDynamicSharedMemorySize, 65536);

  dim3 cg(16, 8, 32);
  conv_split_kernel<<<cg, 256>>>(enc, dec, out);

  dim3 gg1(16, 8, 16);
  hmma_gemm1_kernel<<<gg1, 256, 98304>>>();

  softmax_pack_kernel<<<dim3(128, 16), 256>>>();

  dim3 gg2(8, 8, 16);
  hmma_gemm2_kernel<<<gg2, 256, 65536>>>(out);
}